// round 13
// baseline (speedup 1.0000x reference)
#include <cuda_runtime.h>
#include <cuda_bf16.h>
#include <math.h>
#include <cstdint>

#define BB 16
#define LL 512
#define HIDN 768
#define HH 12
#define DD 64
#define NSTRUCT 5
#define BH (BB*HH)   // 192

typedef unsigned long long ull;

// ---- warp MMA helpers ----
__device__ __forceinline__ uint32_t smem_u32(const void* p) {
    uint32_t a;
    asm("{ .reg .u64 t; cvta.to.shared.u64 t, %1; cvt.u32.u64 %0, t; }" : "=r"(a) : "l"(p));
    return a;
}
#define LDSM4(r, addr) \
    asm volatile("ldmatrix.sync.aligned.m8n8.x4.shared.b16 {%0,%1,%2,%3}, [%4];" \
        : "=r"((r)[0]), "=r"((r)[1]), "=r"((r)[2]), "=r"((r)[3]) : "r"(addr))

__device__ __forceinline__ void mma_bf16(float* c, const uint32_t* a, const uint32_t* b) {
    asm volatile("mma.sync.aligned.m16n8k16.row.col.f32.bf16.bf16.f32 "
        "{%0,%1,%2,%3}, {%4,%5,%6,%7}, {%8,%9}, {%0,%1,%2,%3};"
        : "+f"(c[0]), "+f"(c[1]), "+f"(c[2]), "+f"(c[3])
        : "r"(a[0]), "r"(a[1]), "r"(a[2]), "r"(a[3]), "r"(b[0]), "r"(b[1]));
}
#define CP_ASYNC16(sa, gp) \
    asm volatile("cp.async.cg.shared.global [%0], [%1], 16;" :: "r"(sa), "l"(gp))
#define CP_COMMIT() asm volatile("cp.async.commit_group;" ::: "memory")
#define CP_WAIT1()  asm volatile("cp.async.wait_group 1;" ::: "memory")
#define CP_WAIT0()  asm volatile("cp.async.wait_group 0;" ::: "memory")

// ---------------- scratch ----------------
__device__ float    g_Q [BH * LL * DD];            // fp32 Q (qb_kernel input)
__device__ unsigned g_MB[NSTRUCT * BB * LL * (LL/32)];
__device__ __nv_bfloat16 g_hsH[BB*LL*HIDN], g_hsL[BB*LL*HIDN];
__device__ __nv_bfloat16 g_WH [3*HIDN*HIDN], g_WL [3*HIDN*HIDN];
// pre-split bf16 operands for attention MMA
__device__ __nv_bfloat16 g_QH [BH * LL * DD], g_QL [BH * LL * DD];
__device__ __nv_bfloat16 g_KH [BH * LL * DD], g_KL [BH * LL * DD];
__device__ __nv_bfloat16 g_QBH[NSTRUCT * BH * LL * DD], g_QBL[NSTRUCT * BH * LL * DD];
// V transposed [bh][d][l], bf16 split (PV MMA B operand)
__device__ __nv_bfloat16 g_VTH[BH * DD * LL], g_VTL[BH * DD * LL];

// =============================================================================
// Kernel 0a: pack structure mask to bits.
// =============================================================================
__global__ void __launch_bounds__(256) pack_mask(const float* __restrict__ smask)
{
    size_t e = (size_t)blockIdx.x * 256 + threadIdx.x;
    float v = smask[e];
    unsigned bal = __ballot_sync(0xffffffffu, v != 0.f);
    if ((threadIdx.x & 31) == 0) g_MB[e >> 5] = bal;
}

// =============================================================================
// split helpers
// =============================================================================
__device__ __forceinline__ void split2(float a, float b, __nv_bfloat162* H, __nv_bfloat162* L) {
    __nv_bfloat16 ah = __float2bfloat16_rn(a), bh = __float2bfloat16_rn(b);
    __nv_bfloat16 al = __float2bfloat16_rn(a - __bfloat162float(ah));
    __nv_bfloat16 bl = __float2bfloat16_rn(b - __bfloat162float(bh));
    *H = __nv_bfloat162(ah, bh);
    *L = __nv_bfloat162(al, bl);
}
__global__ void __launch_bounds__(256) cvt_hs(const float* __restrict__ hs)
{
    size_t i = (size_t)blockIdx.x * 256 + threadIdx.x;
    float4 v = ((const float4*)hs)[i];
    __nv_bfloat162 h0, l0, h1, l1;
    split2(v.x, v.y, &h0, &l0);
    split2(v.z, v.w, &h1, &l1);
    ((__nv_bfloat162*)g_hsH)[2*i]   = h0;
    ((__nv_bfloat162*)g_hsH)[2*i+1] = h1;
    ((__nv_bfloat162*)g_hsL)[2*i]   = l0;
    ((__nv_bfloat162*)g_hsL)[2*i+1] = l1;
}
__global__ void __launch_bounds__(256) cvt_w(const float* __restrict__ Wq,
                                             const float* __restrict__ Wk,
                                             const float* __restrict__ Wv)
{
    size_t i = (size_t)blockIdx.x * 256 + threadIdx.x;
    const size_t per = (size_t)HIDN*HIDN/4;
    const float* src = (i < per) ? Wq : (i < 2*per) ? Wk : Wv;
    size_t loc = i % per;
    float4 v = ((const float4*)src)[loc];
    __nv_bfloat162 h0, l0, h1, l1;
    split2(v.x, v.y, &h0, &l0);
    split2(v.z, v.w, &h1, &l1);
    ((__nv_bfloat162*)g_WH)[2*i]   = h0;
    ((__nv_bfloat162*)g_WH)[2*i+1] = h1;
    ((__nv_bfloat162*)g_WL)[2*i]   = l0;
    ((__nv_bfloat162*)g_WL)[2*i+1] = l1;
}

// =============================================================================
// Kernel 1: QKV projection on mma.sync bf16 (split bf16x3).
// z=0 -> fp32 g_Q + split g_QH/QL; z=1 -> split g_KH/KL; z=2 -> split V^T.
// =============================================================================
#define QT_ROWB 80
#define QT_TILE (128 * QT_ROWB)
#define QT_STAGE (4 * QT_TILE)
#define QT_SMEM (2 * QT_STAGE)
#define NCHUNK (HIDN / 32)

__global__ void __launch_bounds__(256) qkv_mma_kernel(
    const float* __restrict__ bq, const float* __restrict__ bk, const float* __restrict__ bv)
{
    extern __shared__ __align__(16) char smem[];
    const uint32_t sb = smem_u32(smem);

    const int t = threadIdx.x, wid = t >> 5, lane = t & 31;
    const int m0 = blockIdx.x * 128;
    const int n0 = blockIdx.y * 128;
    const int z  = blockIdx.z;
    const float* bias = (z == 0) ? bq : (z == 1) ? bk : bv;
    const __nv_bfloat16* BHg = g_WH + (size_t)z * HIDN * HIDN;
    const __nv_bfloat16* BLg = g_WL + (size_t)z * HIDN * HIDN;

    const int wm = (wid & 1) * 64;
    const int wn = (wid >> 1) * 32;

    float C[4][4][4];
#pragma unroll
    for (int i = 0; i < 4; i++)
#pragma unroll
        for (int j = 0; j < 4; j++)
#pragma unroll
            for (int k = 0; k < 4; k++) C[i][j][k] = 0.f;

    const uint32_t a_off = (uint32_t)((wm + (lane & 7) + ((lane >> 3) & 1) * 8) * QT_ROWB
                                      + ((lane >> 4) * 8) * 2);
    const uint32_t b_off = (uint32_t)((wn + (lane & 7) + (lane >> 4) * 8) * QT_ROWB
                                      + (((lane >> 3) & 1) * 8) * 2);

    const int lr0 = t >> 2, lu0 = t & 3;
    const int lr1 = (t + 256) >> 2, lu1 = t & 3;

    {
        const int k0 = 0;
        uint32_t s0 = sb;
#pragma unroll
        for (int p = 0; p < 2; ++p) {
            int r = p ? lr1 : lr0, u = p ? lu1 : lu0;
            uint32_t so = (uint32_t)(r * QT_ROWB + u * 16);
            size_t ga = (size_t)(m0 + r) * HIDN + k0 + u * 8;
            size_t gb = (size_t)(n0 + r) * HIDN + k0 + u * 8;
            CP_ASYNC16(s0 + 0*QT_TILE + so, g_hsH + ga);
            CP_ASYNC16(s0 + 1*QT_TILE + so, g_hsL + ga);
            CP_ASYNC16(s0 + 2*QT_TILE + so, BHg + gb);
            CP_ASYNC16(s0 + 3*QT_TILE + so, BLg + gb);
        }
        CP_COMMIT();
    }

    for (int ch = 0; ch < NCHUNK; ++ch) {
        if (ch + 1 < NCHUNK) {
            const int k0 = (ch + 1) * 32;
            uint32_t s1 = sb + ((ch + 1) & 1) * QT_STAGE;
#pragma unroll
            for (int p = 0; p < 2; ++p) {
                int r = p ? lr1 : lr0, u = p ? lu1 : lu0;
                uint32_t so = (uint32_t)(r * QT_ROWB + u * 16);
                size_t ga = (size_t)(m0 + r) * HIDN + k0 + u * 8;
                size_t gb = (size_t)(n0 + r) * HIDN + k0 + u * 8;
                CP_ASYNC16(s1 + 0*QT_TILE + so, g_hsH + ga);
                CP_ASYNC16(s1 + 1*QT_TILE + so, g_hsL + ga);
                CP_ASYNC16(s1 + 2*QT_TILE + so, BHg + gb);
                CP_ASYNC16(s1 + 3*QT_TILE + so, BLg + gb);
            }
            CP_COMMIT();
            CP_WAIT1();
        } else {
            CP_WAIT0();
        }
        __syncthreads();

        const uint32_t st = sb + (ch & 1) * QT_STAGE;
        const uint32_t aH = st + 0*QT_TILE + a_off;
        const uint32_t aL = st + 1*QT_TILE + a_off;
        const uint32_t bHb = st + 2*QT_TILE + b_off;
        const uint32_t bLb = st + 3*QT_TILE + b_off;

#pragma unroll
        for (int ks = 0; ks < 2; ++ks) {
            const uint32_t ko = ks * 32;
            uint32_t ah[4][4], al[4][4], bh[4][2], bl[4][2];
#pragma unroll
            for (int mt = 0; mt < 4; ++mt) {
                LDSM4(ah[mt], aH + mt * 16 * QT_ROWB + ko);
                LDSM4(al[mt], aL + mt * 16 * QT_ROWB + ko);
            }
#pragma unroll
            for (int p = 0; p < 2; ++p) {
                uint32_t r4[4];
                LDSM4(r4, bHb + p * 16 * QT_ROWB + ko);
                bh[2*p][0] = r4[0]; bh[2*p][1] = r4[1];
                bh[2*p+1][0] = r4[2]; bh[2*p+1][1] = r4[3];
                LDSM4(r4, bLb + p * 16 * QT_ROWB + ko);
                bl[2*p][0] = r4[0]; bl[2*p][1] = r4[1];
                bl[2*p+1][0] = r4[2]; bl[2*p+1][1] = r4[3];
            }
#pragma unroll
            for (int mt = 0; mt < 4; ++mt)
#pragma unroll
                for (int nt = 0; nt < 4; ++nt) {
                    mma_bf16(C[mt][nt], ah[mt], bh[nt]);
                    mma_bf16(C[mt][nt], ah[mt], bl[nt]);
                    mma_bf16(C[mt][nt], al[mt], bh[nt]);
                }
        }
        __syncthreads();
    }

    // ---- epilogue ----
#pragma unroll
    for (int mt = 0; mt < 4; ++mt) {
        const int m = m0 + wm + mt * 16 + (lane >> 2);
        const int b = m >> 9, l = m & 511;
#pragma unroll
        for (int nt = 0; nt < 4; ++nt) {
            const int n = n0 + wn + nt * 8 + (lane & 3) * 2;
            const int hd = n >> 6, d = n & 63;
            const float b0 = __ldg(bias + n), b1 = __ldg(bias + n + 1);
            float v00 = C[mt][nt][0] + b0, v01 = C[mt][nt][1] + b1;
            float v10 = C[mt][nt][2] + b0, v11 = C[mt][nt][3] + b1;
            if (z == 2) {
                // V^T split: [bh][d][l]
                const size_t vb = (size_t)(b * HH + hd) * DD;
                __nv_bfloat16 h00 = __float2bfloat16_rn(v00);
                __nv_bfloat16 h01 = __float2bfloat16_rn(v01);
                __nv_bfloat16 h10 = __float2bfloat16_rn(v10);
                __nv_bfloat16 h11 = __float2bfloat16_rn(v11);
                g_VTH[(vb + d)     * LL + l]     = h00;
                g_VTH[(vb + d + 1) * LL + l]     = h01;
                g_VTH[(vb + d)     * LL + l + 8] = h10;
                g_VTH[(vb + d + 1) * LL + l + 8] = h11;
                g_VTL[(vb + d)     * LL + l]     = __float2bfloat16_rn(v00 - __bfloat162float(h00));
                g_VTL[(vb + d + 1) * LL + l]     = __float2bfloat16_rn(v01 - __bfloat162float(h01));
                g_VTL[(vb + d)     * LL + l + 8] = __float2bfloat16_rn(v10 - __bfloat162float(h10));
                g_VTL[(vb + d + 1) * LL + l + 8] = __float2bfloat16_rn(v11 - __bfloat162float(h11));
            } else {
                const size_t o1 = ((size_t)(b * HH + hd) * LL + l) * DD + d;
                const size_t o2 = ((size_t)(b * HH + hd) * LL + (l + 8)) * DD + d;
                __nv_bfloat16* dH = (z == 0) ? g_QH : g_KH;
                __nv_bfloat16* dL = (z == 0) ? g_QL : g_KL;
                if (z == 0) {
                    *(float2*)(g_Q + o1) = make_float2(v00, v01);
                    *(float2*)(g_Q + o2) = make_float2(v10, v11);
                }
                __nv_bfloat162 hh, llo;
                split2(v00, v01, &hh, &llo);
                *(__nv_bfloat162*)(dH + o1) = hh;
                *(__nv_bfloat162*)(dL + o1) = llo;
                split2(v10, v11, &hh, &llo);
                *(__nv_bfloat162*)(dH + o2) = hh;
                *(__nv_bfloat162*)(dL + o2) = llo;
            }
        }
    }
}

// =============================================================================
// Kernel 2: QB = Q @ bili (SIMT), pre-split bf16 output.
// =============================================================================
__global__ void __launch_bounds__(256) qb_kernel(const float* __restrict__ bili)
{
    const int mt = blockIdx.x, h = blockIdx.y, s = blockIdx.z;
    const int m0 = mt * 64;
    const int b = m0 >> 9, l0 = m0 & 511;
    const float* qbase = g_Q + (size_t)(b*HH + h) * LL * DD;
    const float* Bm    = bili + (size_t)(s*HH + h) * DD * DD;
    const size_t dstoff = (size_t)((s*BB + b)*HH + h) * LL * DD;

    __shared__ __align__(16) float As[16 * 68];
    __shared__ __align__(16) float Bs[16 * 68];

    const int t = threadIdx.x;
    const int mload = t >> 2, kv = t & 3;
    const int kl = t >> 4, nv = t & 15;
    const int ty = t >> 4, tx = t & 15;

    float c[4][4];
#pragma unroll
    for (int i = 0; i < 4; i++)
#pragma unroll
        for (int j = 0; j < 4; j++) c[i][j] = 0.f;

    for (int k0 = 0; k0 < DD; k0 += 16) {
        float4 a4 = *(const float4*)(qbase + (size_t)(l0 + mload) * DD + k0 + kv * 4);
        As[(kv*4+0)*68 + mload] = a4.x;
        As[(kv*4+1)*68 + mload] = a4.y;
        As[(kv*4+2)*68 + mload] = a4.z;
        As[(kv*4+3)*68 + mload] = a4.w;
        float4 b4 = *(const float4*)(Bm + (size_t)(k0 + kl) * DD + nv * 4);
        Bs[kl*68 + nv*4+0] = b4.x;
        Bs[kl*68 + nv*4+1] = b4.y;
        Bs[kl*68 + nv*4+2] = b4.z;
        Bs[kl*68 + nv*4+3] = b4.w;
        __syncthreads();
#pragma unroll
        for (int k = 0; k < 16; k++) {
            float4 av4 = *(const float4*)&As[k*68 + ty*4];
            float4 bv4 = *(const float4*)&Bs[k*68 + tx*4];
            float a[4] = {av4.x, av4.y, av4.z, av4.w};
            float bb[4] = {bv4.x, bv4.y, bv4.z, bv4.w};
#pragma unroll
            for (int i = 0; i < 4; i++)
#pragma unroll
                for (int j = 0; j < 4; j++) c[i][j] += a[i] * bb[j];
        }
        __syncthreads();
    }

#pragma unroll
    for (int i = 0; i < 4; i++) {
        const size_t ro = dstoff + (size_t)(l0 + ty*4 + i) * DD + tx*4;
        __nv_bfloat162 h0, l0b, h1, l1b;
        split2(c[i][0], c[i][1], &h0, &l0b);
        split2(c[i][2], c[i][3], &h1, &l1b);
        uint2 hv, lv;
        hv.x = *(uint32_t*)&h0; hv.y = *(uint32_t*)&h1;
        lv.x = *(uint32_t*)&l0b; lv.y = *(uint32_t*)&l1b;
        *(uint2*)(g_QBH + ro) = hv;
        *(uint2*)(g_QBL + ro) = lv;
    }
}

// =============================================================================
// Kernel 3: fused attention, FA2-style register-resident scores/probs.
// Block = 64 q-rows; 8 warps = 4 row-groups (16 rows) x 2 col-halves (64 of 128).
// S/P/O live in fragments; softmax = quad shuffles + tiny smem exchange.
// PV = MMA with P,V bf16 hi/lo split.
// =============================================================================
#define A_QH 0
#define A_QL (A_QH + 6*64*144)          // 55296
#define A_KH (A_QL + 6*64*144)          // 110592
#define A_KL (A_KH + 128*144)           // 129024
#define A_VH (A_KL + 128*144)           // 147456
#define A_VL (A_VH + 64*272)            // 164864
#define A_AM (A_VL + 64*272)            // 182272
#define A_RED (A_AM + 512)              // 182784
#define A_EXCH A_KH                     // reuse K region for O exchange
#define A_TOT (A_RED + 1024)            // 183808

__global__ void __launch_bounds__(256) attn_kernel(
    const float* __restrict__ amask,
    const float* __restrict__ absb,
    float* __restrict__ out)
{
    extern __shared__ __align__(16) char smem[];
    const uint32_t sb = smem_u32(smem);

    const int t    = threadIdx.x;
    const int w    = t >> 5;
    const int lane = t & 31;
    const int bh   = blockIdx.y;
    const int b = bh / HH, h = bh % HH;
    const int i0 = blockIdx.x * 64;

    const int wg = w >> 1;          // row group 0..3
    const int ch = w & 1;           // col half 0..1
    const int row0 = wg * 16;

    const __nv_bfloat16* KHb = g_KH + (size_t)bh * LL * DD;
    const __nv_bfloat16* KLb = g_KL + (size_t)bh * LL * DD;
    const __nv_bfloat16* VHb = g_VTH + (size_t)bh * DD * LL;
    const __nv_bfloat16* VLb = g_VTL + (size_t)bh * DD * LL;

    // ---- load q + 5 qb components (pre-split bf16) ----
    for (int f = t; f < 6 * 64 * 8; f += 256) {
        int c = f >> 9;
        int r = (f >> 3) & 63;
        int u = f & 7;
        const size_t go = (c == 0)
            ? (size_t)bh * LL * DD + (size_t)(i0 + r) * DD + u * 8
            : (size_t)((c - 1) * BB + b) * HH * LL * DD + (size_t)h * LL * DD
              + (size_t)(i0 + r) * DD + u * 8;
        const __nv_bfloat16* sH = (c == 0) ? (g_QH + go) : (g_QBH + go);
        const __nv_bfloat16* sL = (c == 0) ? (g_QL + go) : (g_QBL + go);
        char* p = smem + (c * 64 + r) * 144 + u * 16;
        *(uint4*)(p + A_QH) = *(const uint4*)sH;
        *(uint4*)(p + A_QL) = *(const uint4*)sL;
    }

    float ab[NSTRUCT];
#pragma unroll
    for (int s = 0; s < NSTRUCT; ++s) ab[s] = __ldg(absb + s*HH + h);

    float mrow[2] = {-1e30f, -1e30f};
    float lrow[2] = {0.f, 0.f};
    float Ofr[8][4];
#pragma unroll
    for (int nt = 0; nt < 8; ++nt)
#pragma unroll
        for (int k = 0; k < 4; ++k) Ofr[nt][k] = 0.f;

    const uint32_t a_base = sb + A_QH
        + (uint32_t)((row0 + (lane & 7) + ((lane >> 3) & 1) * 8) * 144 + (lane >> 4) * 16);
    const uint32_t bk_base = sb + A_KH
        + (uint32_t)((ch * 64 + (lane & 7) + (lane >> 4) * 8) * 144 + ((lane >> 3) & 1) * 16);
    const uint32_t bv_base = sb + A_VH
        + (uint32_t)(((lane & 7) + (lane >> 4) * 8) * 272 + ((lane >> 3) & 1) * 16 + ch * 128);
    const uint32_t QLOFF = A_QL - A_QH;
    const uint32_t KLOFF = A_KL - A_KH;
    const uint32_t VLOFF = A_VL - A_VH;

    const int rquad = lane >> 2;      // local row 0..7 (and +8)
    const int cpair = (lane & 3) * 2;

    for (int jt = 0; jt < 4; ++jt) {
        const int j0 = jt * 128;
        __syncthreads();
        // ---- load K tile (128 rows x 64 d, split) ----
        for (int f = t; f < 128 * 8; f += 256) {
            int j = f >> 3, u = f & 7;
            const size_t go = (size_t)(j0 + j) * DD + u * 8;
            char* p = smem + j * 144 + u * 16;
            *(uint4*)(p + A_KH) = *(const uint4*)(KHb + go);
            *(uint4*)(p + A_KL) = *(const uint4*)(KLb + go);
        }
        // ---- load V^T tile (64 d-rows x 128 j-cols, split, stride 272) ----
        for (int f = t; f < 64 * 16; f += 256) {
            int d = f >> 4, u = f & 15;
            const size_t go = (size_t)d * LL + j0 + u * 8;
            char* p = smem + d * 272 + u * 16;
            *(uint4*)(p + A_VH) = *(const uint4*)(VHb + go);
            *(uint4*)(p + A_VL) = *(const uint4*)(VLb + go);
        }
        if (t < 32)
            *(float4*)(smem + A_AM + t * 16) =
                *(const float4*)(amask + (size_t)b * LL + j0 + t * 4);
        __syncthreads();

        // ---- S accumulation: paired components, B frags shared within pair ----
        float S[8][4];
#pragma unroll
        for (int nt = 0; nt < 8; ++nt)
#pragma unroll
            for (int k = 0; k < 4; ++k) S[nt][k] = 0.f;

#pragma unroll
        for (int pr = 0; pr < 3; ++pr) {
            const int ca = 2 * pr, cb = 2 * pr + 1;
            float Ta[8][4], Tb[8][4];
#pragma unroll
            for (int nt = 0; nt < 8; ++nt)
#pragma unroll
                for (int k = 0; k < 4; ++k) { Ta[nt][k] = 0.f; Tb[nt][k] = 0.f; }

            const uint32_t aHa = a_base + (uint32_t)(ca * 64 * 144);
            const uint32_t aHb = a_base + (uint32_t)(cb * 64 * 144);
#pragma unroll
            for (int ks = 0; ks < 4; ++ks) {
                const uint32_t ko = ks * 32;
                uint32_t bhf[8][2], blf[8][2];
#pragma unroll
                for (int p = 0; p < 4; ++p) {
                    uint32_t r4[4];
                    LDSM4(r4, bk_base + p * 16 * 144 + ko);
                    bhf[2*p][0] = r4[0]; bhf[2*p][1] = r4[1];
                    bhf[2*p+1][0] = r4[2]; bhf[2*p+1][1] = r4[3];
                    LDSM4(r4, bk_base + KLOFF + p * 16 * 144 + ko);
                    blf[2*p][0] = r4[0]; blf[2*p][1] = r4[1];
                    blf[2*p+1][0] = r4[2]; blf[2*p+1][1] = r4[3];
                }
                uint32_t ah[4], al[4];
                LDSM4(ah, aHa + ko);
                LDSM4(al, aHa + QLOFF + ko);
#pragma unroll
                for (int nt = 0; nt < 8; ++nt) {
                    mma_bf16(Ta[nt], ah, bhf[nt]);
                    mma_bf16(Ta[nt], ah, blf[nt]);
                    mma_bf16(Ta[nt], al, bhf[nt]);
                }
                LDSM4(ah, aHb + ko);
                LDSM4(al, aHb + QLOFF + ko);
#pragma unroll
                for (int nt = 0; nt < 8; ++nt) {
                    mma_bf16(Tb[nt], ah, bhf[nt]);
                    mma_bf16(Tb[nt], ah, blf[nt]);
                    mma_bf16(Tb[nt], al, bhf[nt]);
                }
            }

            // ---- combine Ta ----
            if (ca == 0) {
#pragma unroll
                for (int nt = 0; nt < 8; ++nt)
#pragma unroll
                    for (int k = 0; k < 4; ++k) S[nt][k] += Ta[nt][k];
            } else {
                const int s = ca - 1;
                const float abs_s = ab[s];
                const int wi0 = (j0 >> 5) + ch * 2;
                const size_t baseA = ((size_t)(s*BB + b) * LL + i0 + row0 + rquad) * 16;
                const size_t baseB = baseA + 8 * 16;
                unsigned mA0 = g_MB[baseA + wi0], mA1 = g_MB[baseA + wi0 + 1];
                unsigned mB0 = g_MB[baseB + wi0], mB1 = g_MB[baseB + wi0 + 1];
#pragma unroll
                for (int nt = 0; nt < 8; ++nt) {
                    const unsigned wA = (nt < 4) ? mA0 : mA1;
                    const unsigned wB = (nt < 4) ? mB0 : mB1;
                    const int bp = (nt & 3) * 8 + cpair;
                    S[nt][0] += (float)((wA >> bp) & 1u)     * (Ta[nt][0] + abs_s);
                    S[nt][1] += (float)((wA >> (bp+1)) & 1u) * (Ta[nt][1] + abs_s);
                    S[nt][2] += (float)((wB >> bp) & 1u)     * (Ta[nt][2] + abs_s);
                    S[nt][3] += (float)((wB >> (bp+1)) & 1u) * (Ta[nt][3] + abs_s);
                }
            }
            // ---- combine Tb (cb = 1,3,5) ----
            {
                const int s = cb - 1;
                const float abs_s = ab[s];
                const int wi0 = (j0 >> 5) + ch * 2;
                const size_t baseA = ((size_t)(s*BB + b) * LL + i0 + row0 + rquad) * 16;
                const size_t baseB = baseA + 8 * 16;
                unsigned mA0 = g_MB[baseA + wi0], mA1 = g_MB[baseA + wi0 + 1];
                unsigned mB0 = g_MB[baseB + wi0], mB1 = g_MB[baseB + wi0 + 1];
#pragma unroll
                for (int nt = 0; nt < 8; ++nt) {
                    const unsigned wA = (nt < 4) ? mA0 : mA1;
                    const unsigned wB = (nt < 4) ? mB0 : mB1;
                    const int bp = (nt & 3) * 8 + cpair;
                    S[nt][0] += (float)((wA >> bp) & 1u)     * (Tb[nt][0] + abs_s);
                    S[nt][1] += (float)((wA >> (bp+1)) & 1u) * (Tb[nt][1] + abs_s);
                    S[nt][2] += (float)((wB >> bp) & 1u)     * (Tb[nt][2] + abs_s);
                    S[nt][3] += (float)((wB >> (bp+1)) & 1u) * (Tb[nt][3] + abs_s);
                }
            }
        }

        // ---- logits + local (partial) softmax in registers ----
        float pmax0 = -1e30f, pmax1 = -1e30f;
#pragma unroll
        for (int nt = 0; nt < 8; ++nt) {
            float2 am2 = *(float2*)(smem + A_AM + (ch * 64 + nt * 8 + cpair) * 4);
            S[nt][0] = S[nt][0] * 0.125f + am2.x;
            S[nt][1] = S[nt][1] * 0.125f + am2.y;
            S[nt][2] = S[nt][2] * 0.125f + am2.x;
            S[nt][3] = S[nt][3] * 0.125f + am2.y;
            pmax0 = fmaxf(pmax0, fmaxf(S[nt][0], S[nt][1]));
            pmax1 = fmaxf(pmax1, fmaxf(S[nt][2], S[nt][3]));
        }
#pragma unroll
        for (int off = 1; off <= 2; off <<= 1) {
            pmax0 = fmaxf(pmax0, __shfl_xor_sync(0xffffffffu, pmax0, off));
            pmax1 = fmaxf(pmax1, __shfl_xor_sync(0xffffffffu, pmax1, off));
        }
        float ps0 = 0.f, ps1 = 0.f;
#pragma unroll
        for (int nt = 0; nt < 8; ++nt) {
            S[nt][0] = __expf(S[nt][0] - pmax0); ps0 += S[nt][0];
            S[nt][1] = __expf(S[nt][1] - pmax0); ps0 += S[nt][1];
            S[nt][2] = __expf(S[nt][2] - pmax1); ps1 += S[nt][2];
            S[nt][3] = __expf(S[nt][3] - pmax1); ps1 += S[nt][3];
        }
#pragma unroll
        for (int off = 1; off <= 2; off <<= 1) {
            ps0 += __shfl_xor_sync(0xffffffffu, ps0, off);
            ps1 += __shfl_xor_sync(0xffffffffu, ps1, off);
        }
        if ((lane & 3) == 0) {
            *(float2*)(smem + A_RED + ((row0 + rquad) * 2 + ch) * 8)     = make_float2(pmax0, ps0);
            *(float2*)(smem + A_RED + ((row0 + rquad + 8) * 2 + ch) * 8) = make_float2(pmax1, ps1);
        }
        __syncthreads();
        float2 peer0 = *(float2*)(smem + A_RED + ((row0 + rquad) * 2 + (ch ^ 1)) * 8);
        float2 peer1 = *(float2*)(smem + A_RED + ((row0 + rquad + 8) * 2 + (ch ^ 1)) * 8);

        float mnew0 = fmaxf(mrow[0], fmaxf(pmax0, peer0.x));
        float mnew1 = fmaxf(mrow[1], fmaxf(pmax1, peer1.x));
        float corr0 = __expf(mrow[0] - mnew0);
        float corr1 = __expf(mrow[1] - mnew1);
        float f0 = __expf(pmax0 - mnew0), fp0 = __expf(peer0.x - mnew0);
        float f1 = __expf(pmax1 - mnew1), fp1 = __expf(peer1.x - mnew1);
        lrow[0] = lrow[0] * corr0 + ps0 * f0 + peer0.y * fp0;
        lrow[1] = lrow[1] * corr1 + ps1 * f1 + peer1.y * fp1;
        mrow[0] = mnew0; mrow[1] = mnew1;

#pragma unroll
        for (int nt = 0; nt < 8; ++nt) {
            Ofr[nt][0] *= corr0; Ofr[nt][1] *= corr0;
            Ofr[nt][2] *= corr1; Ofr[nt][3] *= corr1;
            S[nt][0] *= f0; S[nt][1] *= f0;
            S[nt][2] *= f1; S[nt][3] *= f1;
        }

        // ---- PV MMA: P (A operand, FA2 frag identity) x V^T (B operand) ----
#pragma unroll
        for (int kb = 0; kb < 4; ++kb) {
            uint32_t pah[4], pal[4];
            {
                __nv_bfloat162 hh, llo;
                split2(S[2*kb][0],   S[2*kb][1],   &hh, &llo);
                pah[0] = *(uint32_t*)&hh; pal[0] = *(uint32_t*)&llo;
                split2(S[2*kb][2],   S[2*kb][3],   &hh, &llo);
                pah[1] = *(uint32_t*)&hh; pal[1] = *(uint32_t*)&llo;
                split2(S[2*kb+1][0], S[2*kb+1][1], &hh, &llo);
                pah[2] = *(uint32_t*)&hh; pal[2] = *(uint32_t*)&llo;
                split2(S[2*kb+1][2], S[2*kb+1][3], &hh, &llo);
                pah[3] = *(uint32_t*)&hh; pal[3] = *(uint32_t*)&llo;
            }
            const uint32_t ko = kb * 32;
            uint32_t vbh[8][2], vbl[8][2];
#pragma unroll
            for (int p = 0; p < 4; ++p) {
                uint32_t r4[4];
                LDSM4(r4, bv_base + p * 16 * 272 + ko);
                vbh[2*p][0] = r4[0]; vbh[2*p][1] = r4[1];
                vbh[2*p+1][0] = r4[2]; vbh[2*p+1][1] = r4[3];
                LDSM4(r4, bv_base + VLOFF + p * 16 * 272 + ko);
                vbl[2*p][0] = r4[0]; vbl[2*p][1] = r4[1];
                vbl[2*p+1][0] = r4[2]; vbl[2*p+1][1] = r4[3];
            }
#pragma unroll
            for (int nt = 0; nt < 8; ++nt) {
                mma_bf16(Ofr[nt], pah, vbh[nt]);
                mma_bf16(Ofr[nt], pah, vbl[nt]);
                mma_bf16(Ofr[nt], pal, vbh[nt]);
            }
        }
    }

    // ---- cross-col-half O reduction + output ----
    __syncthreads();
    float* ex = (float*)(smem + A_EXCH) + (size_t)wg * 16 * 64;
    if (ch == 1) {
#pragma unroll
        for (int nt = 0; nt < 8; ++nt) {
            const int d = nt * 8 + cpair;
            *(float2*)(ex + rquad * 64 + d)       = make_float2(Ofr[nt][0], Ofr[nt][1]);
            *(float2*)(ex + (rquad + 8) * 64 + d) = make_float2(Ofr[nt][2], Ofr[nt][3]);
        }
    }
    __syncthreads();
    if (ch == 0) {
        const float inv0 = 1.f / lrow[0];
        const float inv1 = 1.f / lrow[1];
        const int ig0 = i0 + row0 + rquad;
        const int ig1 = ig0 + 8;
        float* op0 = out + (size_t)(b * LL + ig0) * (HH*DD) + h * DD;
        float* op1 = out + (size_t)(b * LL + ig1) * (HH*DD) + h * DD;
#pragma unroll
        for (int nt = 0; nt < 8; ++nt) {
            const int d = nt * 8 + cpair;
            float2 e0 = *(float2*)(ex + rquad * 64 + d);
            float2 e1 = *(float2*)(ex + (rquad + 8) * 64 + d);
            *(float2*)(op0 + d) = make_float2((Ofr[nt][0] + e0.x) * inv0,
                                              (Ofr[nt][1] + e0.y) * inv0);
            *(float2*)(op1 + d) = make_float2((Ofr[nt][2] + e1.x) * inv1,
                                              (Ofr[nt][3] + e1.y) * inv1);
        }
    }
}

// =============================================================================
extern "C" void kernel_launch(void* const* d_in, const int* in_sizes, int n_in,
                              void* d_out, int out_size)
{
    const float* hs   = (const float*)d_in[0];
    const float* am   = (const float*)d_in[1];
    const float* smk  = (const float*)d_in[2];
    const float* Wq   = (const float*)d_in[3];
    const float* bq   = (const float*)d_in[4];
    const float* Wk   = (const float*)d_in[5];
    const float* bk   = (const float*)d_in[6];
    const float* Wv   = (const float*)d_in[7];
    const float* bv   = (const float*)d_in[8];
    const float* bili = (const float*)d_in[9];
    const float* absb = (const float*)d_in[10];
    float* out = (float*)d_out;

    pack_mask<<<(NSTRUCT*BB*LL*LL)/256, 256>>>(smk);
    cvt_hs<<<(BB*LL*HIDN/4)/256, 256>>>(hs);
    cvt_w<<<(3*HIDN*HIDN/4)/256, 256>>>(Wq, Wk, Wv);

    cudaFuncSetAttribute(qkv_mma_kernel, cudaFuncAttributeMaxDynamicSharedMemorySize, QT_SMEM);
    qkv_mma_kernel<<<dim3(64, 6, 3), 256, QT_SMEM>>>(bq, bk, bv);

    qb_kernel<<<dim3(128, 12, 5), 256>>>(bili);

    cudaFuncSetAttribute(attn_kernel, cudaFuncAttributeMaxDynamicSharedMemorySize, A_TOT);
    attn_kernel<<<dim3(8, 192), 256, A_TOT>>>(am, absb, out);
}

// round 14
// speedup vs baseline: 1.0036x; 1.0036x over previous
#include <cuda_runtime.h>
#include <cuda_bf16.h>
#include <math.h>
#include <cstdint>

#define BB 16
#define LL 512
#define HIDN 768
#define HH 12
#define DD 64
#define NSTRUCT 5
#define BH (BB*HH)   // 192

typedef unsigned long long ull;

// ---- warp MMA helpers ----
__device__ __forceinline__ uint32_t smem_u32(const void* p) {
    uint32_t a;
    asm("{ .reg .u64 t; cvta.to.shared.u64 t, %1; cvt.u32.u64 %0, t; }" : "=r"(a) : "l"(p));
    return a;
}
#define LDSM4(r, addr) \
    asm volatile("ldmatrix.sync.aligned.m8n8.x4.shared.b16 {%0,%1,%2,%3}, [%4];" \
        : "=r"((r)[0]), "=r"((r)[1]), "=r"((r)[2]), "=r"((r)[3]) : "r"(addr))

__device__ __forceinline__ void mma_bf16(float* c, const uint32_t* a, const uint32_t* b) {
    asm volatile("mma.sync.aligned.m16n8k16.row.col.f32.bf16.bf16.f32 "
        "{%0,%1,%2,%3}, {%4,%5,%6,%7}, {%8,%9}, {%0,%1,%2,%3};"
        : "+f"(c[0]), "+f"(c[1]), "+f"(c[2]), "+f"(c[3])
        : "r"(a[0]), "r"(a[1]), "r"(a[2]), "r"(a[3]), "r"(b[0]), "r"(b[1]));
}
#define CP_ASYNC16(sa, gp) \
    asm volatile("cp.async.cg.shared.global [%0], [%1], 16;" :: "r"(sa), "l"(gp))
#define CP_COMMIT() asm volatile("cp.async.commit_group;" ::: "memory")
#define CP_WAIT1()  asm volatile("cp.async.wait_group 1;" ::: "memory")
#define CP_WAIT0()  asm volatile("cp.async.wait_group 0;" ::: "memory")

// ---------------- scratch ----------------
__device__ float    g_Q [BH * LL * DD];            // fp32 Q (qb_kernel input)
__device__ unsigned g_MB[NSTRUCT * BB * LL * (LL/32)];
__device__ __nv_bfloat16 g_hsH[BB*LL*HIDN], g_hsL[BB*LL*HIDN];
__device__ __nv_bfloat16 g_WH [3*HIDN*HIDN], g_WL [3*HIDN*HIDN];
// pre-split bf16 operands for attention MMA
__device__ __nv_bfloat16 g_QH [BH * LL * DD], g_QL [BH * LL * DD];
__device__ __nv_bfloat16 g_KH [BH * LL * DD], g_KL [BH * LL * DD];
__device__ __nv_bfloat16 g_QBH[NSTRUCT * BH * LL * DD], g_QBL[NSTRUCT * BH * LL * DD];
// V transposed [bh][d][l], bf16 split (PV MMA B operand)
__device__ __nv_bfloat16 g_VTH[BH * DD * LL], g_VTL[BH * DD * LL];

// =============================================================================
// Kernel 0a: pack structure mask to bits.
// =============================================================================
__global__ void __launch_bounds__(256) pack_mask(const float* __restrict__ smask)
{
    size_t e = (size_t)blockIdx.x * 256 + threadIdx.x;
    float v = smask[e];
    unsigned bal = __ballot_sync(0xffffffffu, v != 0.f);
    if ((threadIdx.x & 31) == 0) g_MB[e >> 5] = bal;
}

// =============================================================================
// split helpers
// =============================================================================
__device__ __forceinline__ void split2(float a, float b, __nv_bfloat162* H, __nv_bfloat162* L) {
    __nv_bfloat16 ah = __float2bfloat16_rn(a), bh = __float2bfloat16_rn(b);
    __nv_bfloat16 al = __float2bfloat16_rn(a - __bfloat162float(ah));
    __nv_bfloat16 bl = __float2bfloat16_rn(b - __bfloat162float(bh));
    *H = __nv_bfloat162(ah, bh);
    *L = __nv_bfloat162(al, bl);
}
__global__ void __launch_bounds__(256) cvt_hs(const float* __restrict__ hs)
{
    size_t i = (size_t)blockIdx.x * 256 + threadIdx.x;
    float4 v = ((const float4*)hs)[i];
    __nv_bfloat162 h0, l0, h1, l1;
    split2(v.x, v.y, &h0, &l0);
    split2(v.z, v.w, &h1, &l1);
    ((__nv_bfloat162*)g_hsH)[2*i]   = h0;
    ((__nv_bfloat162*)g_hsH)[2*i+1] = h1;
    ((__nv_bfloat162*)g_hsL)[2*i]   = l0;
    ((__nv_bfloat162*)g_hsL)[2*i+1] = l1;
}
__global__ void __launch_bounds__(256) cvt_w(const float* __restrict__ Wq,
                                             const float* __restrict__ Wk,
                                             const float* __restrict__ Wv)
{
    size_t i = (size_t)blockIdx.x * 256 + threadIdx.x;
    const size_t per = (size_t)HIDN*HIDN/4;
    const float* src = (i < per) ? Wq : (i < 2*per) ? Wk : Wv;
    size_t loc = i % per;
    float4 v = ((const float4*)src)[loc];
    __nv_bfloat162 h0, l0, h1, l1;
    split2(v.x, v.y, &h0, &l0);
    split2(v.z, v.w, &h1, &l1);
    ((__nv_bfloat162*)g_WH)[2*i]   = h0;
    ((__nv_bfloat162*)g_WH)[2*i+1] = h1;
    ((__nv_bfloat162*)g_WL)[2*i]   = l0;
    ((__nv_bfloat162*)g_WL)[2*i+1] = l1;
}

// =============================================================================
// Kernel 1: QKV projection on mma.sync bf16 (split bf16x3), term-outer order.
// z=0 -> fp32 g_Q + split g_QH/QL; z=1 -> split g_KH/KL; z=2 -> split V^T.
// =============================================================================
#define QT_ROWB 80
#define QT_TILE (128 * QT_ROWB)
#define QT_STAGE (4 * QT_TILE)
#define QT_SMEM (2 * QT_STAGE)
#define NCHUNK (HIDN / 32)

__global__ void __launch_bounds__(256) qkv_mma_kernel(
    const float* __restrict__ bq, const float* __restrict__ bk, const float* __restrict__ bv)
{
    extern __shared__ __align__(16) char smem[];
    const uint32_t sb = smem_u32(smem);

    const int t = threadIdx.x, wid = t >> 5, lane = t & 31;
    const int m0 = blockIdx.x * 128;
    const int n0 = blockIdx.y * 128;
    const int z  = blockIdx.z;
    const float* bias = (z == 0) ? bq : (z == 1) ? bk : bv;
    const __nv_bfloat16* BHg = g_WH + (size_t)z * HIDN * HIDN;
    const __nv_bfloat16* BLg = g_WL + (size_t)z * HIDN * HIDN;

    const int wm = (wid & 1) * 64;
    const int wn = (wid >> 1) * 32;

    float C[4][4][4];
#pragma unroll
    for (int i = 0; i < 4; i++)
#pragma unroll
        for (int j = 0; j < 4; j++)
#pragma unroll
            for (int k = 0; k < 4; k++) C[i][j][k] = 0.f;

    const uint32_t a_off = (uint32_t)((wm + (lane & 7) + ((lane >> 3) & 1) * 8) * QT_ROWB
                                      + ((lane >> 4) * 8) * 2);
    const uint32_t b_off = (uint32_t)((wn + (lane & 7) + (lane >> 4) * 8) * QT_ROWB
                                      + (((lane >> 3) & 1) * 8) * 2);

    const int lr0 = t >> 2, lu0 = t & 3;
    const int lr1 = (t + 256) >> 2, lu1 = t & 3;

    {
        const int k0 = 0;
        uint32_t s0 = sb;
#pragma unroll
        for (int p = 0; p < 2; ++p) {
            int r = p ? lr1 : lr0, u = p ? lu1 : lu0;
            uint32_t so = (uint32_t)(r * QT_ROWB + u * 16);
            size_t ga = (size_t)(m0 + r) * HIDN + k0 + u * 8;
            size_t gb = (size_t)(n0 + r) * HIDN + k0 + u * 8;
            CP_ASYNC16(s0 + 0*QT_TILE + so, g_hsH + ga);
            CP_ASYNC16(s0 + 1*QT_TILE + so, g_hsL + ga);
            CP_ASYNC16(s0 + 2*QT_TILE + so, BHg + gb);
            CP_ASYNC16(s0 + 3*QT_TILE + so, BLg + gb);
        }
        CP_COMMIT();
    }

    for (int ch = 0; ch < NCHUNK; ++ch) {
        if (ch + 1 < NCHUNK) {
            const int k0 = (ch + 1) * 32;
            uint32_t s1 = sb + ((ch + 1) & 1) * QT_STAGE;
#pragma unroll
            for (int p = 0; p < 2; ++p) {
                int r = p ? lr1 : lr0, u = p ? lu1 : lu0;
                uint32_t so = (uint32_t)(r * QT_ROWB + u * 16);
                size_t ga = (size_t)(m0 + r) * HIDN + k0 + u * 8;
                size_t gb = (size_t)(n0 + r) * HIDN + k0 + u * 8;
                CP_ASYNC16(s1 + 0*QT_TILE + so, g_hsH + ga);
                CP_ASYNC16(s1 + 1*QT_TILE + so, g_hsL + ga);
                CP_ASYNC16(s1 + 2*QT_TILE + so, BHg + gb);
                CP_ASYNC16(s1 + 3*QT_TILE + so, BLg + gb);
            }
            CP_COMMIT();
            CP_WAIT1();
        } else {
            CP_WAIT0();
        }
        __syncthreads();

        const uint32_t st = sb + (ch & 1) * QT_STAGE;
        const uint32_t aH = st + 0*QT_TILE + a_off;
        const uint32_t aL = st + 1*QT_TILE + a_off;
        const uint32_t bHb = st + 2*QT_TILE + b_off;
        const uint32_t bLb = st + 3*QT_TILE + b_off;

#pragma unroll
        for (int ks = 0; ks < 2; ++ks) {
            const uint32_t ko = ks * 32;
            uint32_t ah[4][4], al[4][4], bh[4][2], bl[4][2];
#pragma unroll
            for (int mt = 0; mt < 4; ++mt) {
                LDSM4(ah[mt], aH + mt * 16 * QT_ROWB + ko);
                LDSM4(al[mt], aL + mt * 16 * QT_ROWB + ko);
            }
#pragma unroll
            for (int p = 0; p < 2; ++p) {
                uint32_t r4[4];
                LDSM4(r4, bHb + p * 16 * QT_ROWB + ko);
                bh[2*p][0] = r4[0]; bh[2*p][1] = r4[1];
                bh[2*p+1][0] = r4[2]; bh[2*p+1][1] = r4[3];
                LDSM4(r4, bLb + p * 16 * QT_ROWB + ko);
                bl[2*p][0] = r4[0]; bl[2*p][1] = r4[1];
                bl[2*p+1][0] = r4[2]; bl[2*p+1][1] = r4[3];
            }
            // term-outer: max accumulator reuse distance (16)
#pragma unroll
            for (int mt = 0; mt < 4; ++mt)
#pragma unroll
                for (int nt = 0; nt < 4; ++nt)
                    mma_bf16(C[mt][nt], ah[mt], bh[nt]);
#pragma unroll
            for (int mt = 0; mt < 4; ++mt)
#pragma unroll
                for (int nt = 0; nt < 4; ++nt)
                    mma_bf16(C[mt][nt], ah[mt], bl[nt]);
#pragma unroll
            for (int mt = 0; mt < 4; ++mt)
#pragma unroll
                for (int nt = 0; nt < 4; ++nt)
                    mma_bf16(C[mt][nt], al[mt], bh[nt]);
        }
        __syncthreads();
    }

    // ---- epilogue ----
#pragma unroll
    for (int mt = 0; mt < 4; ++mt) {
        const int m = m0 + wm + mt * 16 + (lane >> 2);
        const int b = m >> 9, l = m & 511;
#pragma unroll
        for (int nt = 0; nt < 4; ++nt) {
            const int n = n0 + wn + nt * 8 + (lane & 3) * 2;
            const int hd = n >> 6, d = n & 63;
            const float b0 = __ldg(bias + n), b1 = __ldg(bias + n + 1);
            float v00 = C[mt][nt][0] + b0, v01 = C[mt][nt][1] + b1;
            float v10 = C[mt][nt][2] + b0, v11 = C[mt][nt][3] + b1;
            if (z == 2) {
                const size_t vb = (size_t)(b * HH + hd) * DD;
                __nv_bfloat16 h00 = __float2bfloat16_rn(v00);
                __nv_bfloat16 h01 = __float2bfloat16_rn(v01);
                __nv_bfloat16 h10 = __float2bfloat16_rn(v10);
                __nv_bfloat16 h11 = __float2bfloat16_rn(v11);
                g_VTH[(vb + d)     * LL + l]     = h00;
                g_VTH[(vb + d + 1) * LL + l]     = h01;
                g_VTH[(vb + d)     * LL + l + 8] = h10;
                g_VTH[(vb + d + 1) * LL + l + 8] = h11;
                g_VTL[(vb + d)     * LL + l]     = __float2bfloat16_rn(v00 - __bfloat162float(h00));
                g_VTL[(vb + d + 1) * LL + l]     = __float2bfloat16_rn(v01 - __bfloat162float(h01));
                g_VTL[(vb + d)     * LL + l + 8] = __float2bfloat16_rn(v10 - __bfloat162float(h10));
                g_VTL[(vb + d + 1) * LL + l + 8] = __float2bfloat16_rn(v11 - __bfloat162float(h11));
            } else {
                const size_t o1 = ((size_t)(b * HH + hd) * LL + l) * DD + d;
                const size_t o2 = ((size_t)(b * HH + hd) * LL + (l + 8)) * DD + d;
                __nv_bfloat16* dH = (z == 0) ? g_QH : g_KH;
                __nv_bfloat16* dL = (z == 0) ? g_QL : g_KL;
                if (z == 0) {
                    *(float2*)(g_Q + o1) = make_float2(v00, v01);
                    *(float2*)(g_Q + o2) = make_float2(v10, v11);
                }
                __nv_bfloat162 hh, llo;
                split2(v00, v01, &hh, &llo);
                *(__nv_bfloat162*)(dH + o1) = hh;
                *(__nv_bfloat162*)(dL + o1) = llo;
                split2(v10, v11, &hh, &llo);
                *(__nv_bfloat162*)(dH + o2) = hh;
                *(__nv_bfloat162*)(dL + o2) = llo;
            }
        }
    }
}

// =============================================================================
// Kernel 2: QB = Q @ bili (SIMT), pre-split bf16 output.
// =============================================================================
__global__ void __launch_bounds__(256) qb_kernel(const float* __restrict__ bili)
{
    const int mt = blockIdx.x, h = blockIdx.y, s = blockIdx.z;
    const int m0 = mt * 64;
    const int b = m0 >> 9, l0 = m0 & 511;
    const float* qbase = g_Q + (size_t)(b*HH + h) * LL * DD;
    const float* Bm    = bili + (size_t)(s*HH + h) * DD * DD;
    const size_t dstoff = (size_t)((s*BB + b)*HH + h) * LL * DD;

    __shared__ __align__(16) float As[16 * 68];
    __shared__ __align__(16) float Bs[16 * 68];

    const int t = threadIdx.x;
    const int mload = t >> 2, kv = t & 3;
    const int kl = t >> 4, nv = t & 15;
    const int ty = t >> 4, tx = t & 15;

    float c[4][4];
#pragma unroll
    for (int i = 0; i < 4; i++)
#pragma unroll
        for (int j = 0; j < 4; j++) c[i][j] = 0.f;

    for (int k0 = 0; k0 < DD; k0 += 16) {
        float4 a4 = *(const float4*)(qbase + (size_t)(l0 + mload) * DD + k0 + kv * 4);
        As[(kv*4+0)*68 + mload] = a4.x;
        As[(kv*4+1)*68 + mload] = a4.y;
        As[(kv*4+2)*68 + mload] = a4.z;
        As[(kv*4+3)*68 + mload] = a4.w;
        float4 b4 = *(const float4*)(Bm + (size_t)(k0 + kl) * DD + nv * 4);
        Bs[kl*68 + nv*4+0] = b4.x;
        Bs[kl*68 + nv*4+1] = b4.y;
        Bs[kl*68 + nv*4+2] = b4.z;
        Bs[kl*68 + nv*4+3] = b4.w;
        __syncthreads();
#pragma unroll
        for (int k = 0; k < 16; k++) {
            float4 av4 = *(const float4*)&As[k*68 + ty*4];
            float4 bv4 = *(const float4*)&Bs[k*68 + tx*4];
            float a[4] = {av4.x, av4.y, av4.z, av4.w};
            float bb[4] = {bv4.x, bv4.y, bv4.z, bv4.w};
#pragma unroll
            for (int i = 0; i < 4; i++)
#pragma unroll
                for (int j = 0; j < 4; j++) c[i][j] += a[i] * bb[j];
        }
        __syncthreads();
    }

#pragma unroll
    for (int i = 0; i < 4; i++) {
        const size_t ro = dstoff + (size_t)(l0 + ty*4 + i) * DD + tx*4;
        __nv_bfloat162 h0, l0b, h1, l1b;
        split2(c[i][0], c[i][1], &h0, &l0b);
        split2(c[i][2], c[i][3], &h1, &l1b);
        uint2 hv, lv;
        hv.x = *(uint32_t*)&h0; hv.y = *(uint32_t*)&h1;
        lv.x = *(uint32_t*)&l0b; lv.y = *(uint32_t*)&l1b;
        *(uint2*)(g_QBH + ro) = hv;
        *(uint2*)(g_QBL + ro) = lv;
    }
}

// =============================================================================
// Kernel 3: fused attention, FA2-style register-resident, term-outer MMA order.
// Block = 64 q-rows; 8 warps = 4 row-groups x 2 col-halves.
// =============================================================================
#define A_QH 0
#define A_QL (A_QH + 6*64*144)          // 55296
#define A_KH (A_QL + 6*64*144)          // 110592
#define A_KL (A_KH + 128*144)           // 129024
#define A_VH (A_KL + 128*144)           // 147456
#define A_VL (A_VH + 64*272)            // 164864
#define A_AM (A_VL + 64*272)            // 182272
#define A_RED (A_AM + 512)              // 182784
#define A_EXCH A_KH                     // reuse K region for O exchange
#define A_TOT (A_RED + 1024)            // 183808

__global__ void __launch_bounds__(256) attn_kernel(
    const float* __restrict__ amask,
    const float* __restrict__ absb,
    float* __restrict__ out)
{
    extern __shared__ __align__(16) char smem[];
    const uint32_t sb = smem_u32(smem);

    const int t    = threadIdx.x;
    const int w    = t >> 5;
    const int lane = t & 31;
    const int bh   = blockIdx.y;
    const int b = bh / HH, h = bh % HH;
    const int i0 = blockIdx.x * 64;

    const int wg = w >> 1;
    const int ch = w & 1;
    const int row0 = wg * 16;

    const __nv_bfloat16* KHb = g_KH + (size_t)bh * LL * DD;
    const __nv_bfloat16* KLb = g_KL + (size_t)bh * LL * DD;
    const __nv_bfloat16* VHb = g_VTH + (size_t)bh * DD * LL;
    const __nv_bfloat16* VLb = g_VTL + (size_t)bh * DD * LL;

    for (int f = t; f < 6 * 64 * 8; f += 256) {
        int c = f >> 9;
        int r = (f >> 3) & 63;
        int u = f & 7;
        const size_t go = (c == 0)
            ? (size_t)bh * LL * DD + (size_t)(i0 + r) * DD + u * 8
            : (size_t)((c - 1) * BB + b) * HH * LL * DD + (size_t)h * LL * DD
              + (size_t)(i0 + r) * DD + u * 8;
        const __nv_bfloat16* sH = (c == 0) ? (g_QH + go) : (g_QBH + go);
        const __nv_bfloat16* sL = (c == 0) ? (g_QL + go) : (g_QBL + go);
        char* p = smem + (c * 64 + r) * 144 + u * 16;
        *(uint4*)(p + A_QH) = *(const uint4*)sH;
        *(uint4*)(p + A_QL) = *(const uint4*)sL;
    }

    float ab[NSTRUCT];
#pragma unroll
    for (int s = 0; s < NSTRUCT; ++s) ab[s] = __ldg(absb + s*HH + h);

    float mrow[2] = {-1e30f, -1e30f};
    float lrow[2] = {0.f, 0.f};
    float Ofr[8][4];
#pragma unroll
    for (int nt = 0; nt < 8; ++nt)
#pragma unroll
        for (int k = 0; k < 4; ++k) Ofr[nt][k] = 0.f;

    const uint32_t a_base = sb + A_QH
        + (uint32_t)((row0 + (lane & 7) + ((lane >> 3) & 1) * 8) * 144 + (lane >> 4) * 16);
    const uint32_t bk_base = sb + A_KH
        + (uint32_t)((ch * 64 + (lane & 7) + (lane >> 4) * 8) * 144 + ((lane >> 3) & 1) * 16);
    const uint32_t bv_base = sb + A_VH
        + (uint32_t)(((lane & 7) + (lane >> 4) * 8) * 272 + ((lane >> 3) & 1) * 16 + ch * 128);
    const uint32_t QLOFF = A_QL - A_QH;
    const uint32_t KLOFF = A_KL - A_KH;
    const uint32_t VLOFF = A_VL - A_VH;

    const int rquad = lane >> 2;
    const int cpair = (lane & 3) * 2;

    for (int jt = 0; jt < 4; ++jt) {
        const int j0 = jt * 128;
        __syncthreads();
        for (int f = t; f < 128 * 8; f += 256) {
            int j = f >> 3, u = f & 7;
            const size_t go = (size_t)(j0 + j) * DD + u * 8;
            char* p = smem + j * 144 + u * 16;
            *(uint4*)(p + A_KH) = *(const uint4*)(KHb + go);
            *(uint4*)(p + A_KL) = *(const uint4*)(KLb + go);
        }
        for (int f = t; f < 64 * 16; f += 256) {
            int d = f >> 4, u = f & 15;
            const size_t go = (size_t)d * LL + j0 + u * 8;
            char* p = smem + d * 272 + u * 16;
            *(uint4*)(p + A_VH) = *(const uint4*)(VHb + go);
            *(uint4*)(p + A_VL) = *(const uint4*)(VLb + go);
        }
        if (t < 32)
            *(float4*)(smem + A_AM + t * 16) =
                *(const float4*)(amask + (size_t)b * LL + j0 + t * 4);
        __syncthreads();

        // ---- S accumulation: paired components, term-outer MMA order ----
        float S[8][4];
#pragma unroll
        for (int nt = 0; nt < 8; ++nt)
#pragma unroll
            for (int k = 0; k < 4; ++k) S[nt][k] = 0.f;

#pragma unroll
        for (int pr = 0; pr < 3; ++pr) {
            const int ca = 2 * pr, cb = 2 * pr + 1;
            float Ta[8][4], Tb[8][4];
#pragma unroll
            for (int nt = 0; nt < 8; ++nt)
#pragma unroll
                for (int k = 0; k < 4; ++k) { Ta[nt][k] = 0.f; Tb[nt][k] = 0.f; }

            const uint32_t aHa = a_base + (uint32_t)(ca * 64 * 144);
            const uint32_t aHb = a_base + (uint32_t)(cb * 64 * 144);
#pragma unroll
            for (int ks = 0; ks < 4; ++ks) {
                const uint32_t ko = ks * 32;
                uint32_t bhf[8][2], blf[8][2];
#pragma unroll
                for (int p = 0; p < 4; ++p) {
                    uint32_t r4[4];
                    LDSM4(r4, bk_base + p * 16 * 144 + ko);
                    bhf[2*p][0] = r4[0]; bhf[2*p][1] = r4[1];
                    bhf[2*p+1][0] = r4[2]; bhf[2*p+1][1] = r4[3];
                    LDSM4(r4, bk_base + KLOFF + p * 16 * 144 + ko);
                    blf[2*p][0] = r4[0]; blf[2*p][1] = r4[1];
                    blf[2*p+1][0] = r4[2]; blf[2*p+1][1] = r4[3];
                }
                uint32_t ah[4], al[4];
                LDSM4(ah, aHa + ko);
                LDSM4(al, aHa + QLOFF + ko);
                // term-outer for Ta (reuse distance 8)
#pragma unroll
                for (int nt = 0; nt < 8; ++nt) mma_bf16(Ta[nt], ah, bhf[nt]);
#pragma unroll
                for (int nt = 0; nt < 8; ++nt) mma_bf16(Ta[nt], ah, blf[nt]);
#pragma unroll
                for (int nt = 0; nt < 8; ++nt) mma_bf16(Ta[nt], al, bhf[nt]);
                LDSM4(ah, aHb + ko);
                LDSM4(al, aHb + QLOFF + ko);
#pragma unroll
                for (int nt = 0; nt < 8; ++nt) mma_bf16(Tb[nt], ah, bhf[nt]);
#pragma unroll
                for (int nt = 0; nt < 8; ++nt) mma_bf16(Tb[nt], ah, blf[nt]);
#pragma unroll
                for (int nt = 0; nt < 8; ++nt) mma_bf16(Tb[nt], al, bhf[nt]);
            }

            // ---- combine Ta ----
            if (ca == 0) {
#pragma unroll
                for (int nt = 0; nt < 8; ++nt)
#pragma unroll
                    for (int k = 0; k < 4; ++k) S[nt][k] += Ta[nt][k];
            } else {
                const int s = ca - 1;
                const float abs_s = ab[s];
                const int wi0 = (j0 >> 5) + ch * 2;
                const size_t baseA = ((size_t)(s*BB + b) * LL + i0 + row0 + rquad) * 16;
                const size_t baseB = baseA + 8 * 16;
                unsigned mA0 = g_MB[baseA + wi0], mA1 = g_MB[baseA + wi0 + 1];
                unsigned mB0 = g_MB[baseB + wi0], mB1 = g_MB[baseB + wi0 + 1];
#pragma unroll
                for (int nt = 0; nt < 8; ++nt) {
                    const unsigned wA = (nt < 4) ? mA0 : mA1;
                    const unsigned wB = (nt < 4) ? mB0 : mB1;
                    const int bp = (nt & 3) * 8 + cpair;
                    S[nt][0] += (float)((wA >> bp) & 1u)     * (Ta[nt][0] + abs_s);
                    S[nt][1] += (float)((wA >> (bp+1)) & 1u) * (Ta[nt][1] + abs_s);
                    S[nt][2] += (float)((wB >> bp) & 1u)     * (Ta[nt][2] + abs_s);
                    S[nt][3] += (float)((wB >> (bp+1)) & 1u) * (Ta[nt][3] + abs_s);
                }
            }
            // ---- combine Tb (cb = 1,3,5) ----
            {
                const int s = cb - 1;
                const float abs_s = ab[s];
                const int wi0 = (j0 >> 5) + ch * 2;
                const size_t baseA = ((size_t)(s*BB + b) * LL + i0 + row0 + rquad) * 16;
                const size_t baseB = baseA + 8 * 16;
                unsigned mA0 = g_MB[baseA + wi0], mA1 = g_MB[baseA + wi0 + 1];
                unsigned mB0 = g_MB[baseB + wi0], mB1 = g_MB[baseB + wi0 + 1];
#pragma unroll
                for (int nt = 0; nt < 8; ++nt) {
                    const unsigned wA = (nt < 4) ? mA0 : mA1;
                    const unsigned wB = (nt < 4) ? mB0 : mB1;
                    const int bp = (nt & 3) * 8 + cpair;
                    S[nt][0] += (float)((wA >> bp) & 1u)     * (Tb[nt][0] + abs_s);
                    S[nt][1] += (float)((wA >> (bp+1)) & 1u) * (Tb[nt][1] + abs_s);
                    S[nt][2] += (float)((wB >> bp) & 1u)     * (Tb[nt][2] + abs_s);
                    S[nt][3] += (float)((wB >> (bp+1)) & 1u) * (Tb[nt][3] + abs_s);
                }
            }
        }

        // ---- logits + local softmax ----
        float pmax0 = -1e30f, pmax1 = -1e30f;
#pragma unroll
        for (int nt = 0; nt < 8; ++nt) {
            float2 am2 = *(float2*)(smem + A_AM + (ch * 64 + nt * 8 + cpair) * 4);
            S[nt][0] = S[nt][0] * 0.125f + am2.x;
            S[nt][1] = S[nt][1] * 0.125f + am2.y;
            S[nt][2] = S[nt][2] * 0.125f + am2.x;
            S[nt][3] = S[nt][3] * 0.125f + am2.y;
            pmax0 = fmaxf(pmax0, fmaxf(S[nt][0], S[nt][1]));
            pmax1 = fmaxf(pmax1, fmaxf(S[nt][2], S[nt][3]));
        }
#pragma unroll
        for (int off = 1; off <= 2; off <<= 1) {
            pmax0 = fmaxf(pmax0, __shfl_xor_sync(0xffffffffu, pmax0, off));
            pmax1 = fmaxf(pmax1, __shfl_xor_sync(0xffffffffu, pmax1, off));
        }
        float ps0 = 0.f, ps1 = 0.f;
#pragma unroll
        for (int nt = 0; nt < 8; ++nt) {
            S[nt][0] = __expf(S[nt][0] - pmax0); ps0 += S[nt][0];
            S[nt][1] = __expf(S[nt][1] - pmax0); ps0 += S[nt][1];
            S[nt][2] = __expf(S[nt][2] - pmax1); ps1 += S[nt][2];
            S[nt][3] = __expf(S[nt][3] - pmax1); ps1 += S[nt][3];
        }
#pragma unroll
        for (int off = 1; off <= 2; off <<= 1) {
            ps0 += __shfl_xor_sync(0xffffffffu, ps0, off);
            ps1 += __shfl_xor_sync(0xffffffffu, ps1, off);
        }
        if ((lane & 3) == 0) {
            *(float2*)(smem + A_RED + ((row0 + rquad) * 2 + ch) * 8)     = make_float2(pmax0, ps0);
            *(float2*)(smem + A_RED + ((row0 + rquad + 8) * 2 + ch) * 8) = make_float2(pmax1, ps1);
        }
        __syncthreads();
        float2 peer0 = *(float2*)(smem + A_RED + ((row0 + rquad) * 2 + (ch ^ 1)) * 8);
        float2 peer1 = *(float2*)(smem + A_RED + ((row0 + rquad + 8) * 2 + (ch ^ 1)) * 8);

        float mnew0 = fmaxf(mrow[0], fmaxf(pmax0, peer0.x));
        float mnew1 = fmaxf(mrow[1], fmaxf(pmax1, peer1.x));
        float corr0 = __expf(mrow[0] - mnew0);
        float corr1 = __expf(mrow[1] - mnew1);
        float f0 = __expf(pmax0 - mnew0), fp0 = __expf(peer0.x - mnew0);
        float f1 = __expf(pmax1 - mnew1), fp1 = __expf(peer1.x - mnew1);
        lrow[0] = lrow[0] * corr0 + ps0 * f0 + peer0.y * fp0;
        lrow[1] = lrow[1] * corr1 + ps1 * f1 + peer1.y * fp1;
        mrow[0] = mnew0; mrow[1] = mnew1;

#pragma unroll
        for (int nt = 0; nt < 8; ++nt) {
            Ofr[nt][0] *= corr0; Ofr[nt][1] *= corr0;
            Ofr[nt][2] *= corr1; Ofr[nt][3] *= corr1;
            S[nt][0] *= f0; S[nt][1] *= f0;
            S[nt][2] *= f1; S[nt][3] *= f1;
        }

        // ---- PV MMA (term-outer) ----
#pragma unroll
        for (int kb = 0; kb < 4; ++kb) {
            uint32_t pah[4], pal[4];
            {
                __nv_bfloat162 hh, llo;
                split2(S[2*kb][0],   S[2*kb][1],   &hh, &llo);
                pah[0] = *(uint32_t*)&hh; pal[0] = *(uint32_t*)&llo;
                split2(S[2*kb][2],   S[2*kb][3],   &hh, &llo);
                pah[1] = *(uint32_t*)&hh; pal[1] = *(uint32_t*)&llo;
                split2(S[2*kb+1][0], S[2*kb+1][1], &hh, &llo);
                pah[2] = *(uint32_t*)&hh; pal[2] = *(uint32_t*)&llo;
                split2(S[2*kb+1][2], S[2*kb+1][3], &hh, &llo);
                pah[3] = *(uint32_t*)&hh; pal[3] = *(uint32_t*)&llo;
            }
            const uint32_t ko = kb * 32;
            uint32_t vbh[8][2], vbl[8][2];
#pragma unroll
            for (int p = 0; p < 4; ++p) {
                uint32_t r4[4];
                LDSM4(r4, bv_base + p * 16 * 272 + ko);
                vbh[2*p][0] = r4[0]; vbh[2*p][1] = r4[1];
                vbh[2*p+1][0] = r4[2]; vbh[2*p+1][1] = r4[3];
                LDSM4(r4, bv_base + VLOFF + p * 16 * 272 + ko);
                vbl[2*p][0] = r4[0]; vbl[2*p][1] = r4[1];
                vbl[2*p+1][0] = r4[2]; vbl[2*p+1][1] = r4[3];
            }
#pragma unroll
            for (int nt = 0; nt < 8; ++nt) mma_bf16(Ofr[nt], pah, vbh[nt]);
#pragma unroll
            for (int nt = 0; nt < 8; ++nt) mma_bf16(Ofr[nt], pah, vbl[nt]);
#pragma unroll
            for (int nt = 0; nt < 8; ++nt) mma_bf16(Ofr[nt], pal, vbh[nt]);
        }
    }

    // ---- cross-col-half O reduction + output ----
    __syncthreads();
    float* ex = (float*)(smem + A_EXCH) + (size_t)wg * 16 * 64;
    if (ch == 1) {
#pragma unroll
        for (int nt = 0; nt < 8; ++nt) {
            const int d = nt * 8 + cpair;
            *(float2*)(ex + rquad * 64 + d)       = make_float2(Ofr[nt][0], Ofr[nt][1]);
            *(float2*)(ex + (rquad + 8) * 64 + d) = make_float2(Ofr[nt][2], Ofr[nt][3]);
        }
    }
    __syncthreads();
    if (ch == 0) {
        const float inv0 = 1.f / lrow[0];
        const float inv1 = 1.f / lrow[1];
        const int ig0 = i0 + row0 + rquad;
        const int ig1 = ig0 + 8;
        float* op0 = out + (size_t)(b * LL + ig0) * (HH*DD) + h * DD;
        float* op1 = out + (size_t)(b * LL + ig1) * (HH*DD) + h * DD;
#pragma unroll
        for (int nt = 0; nt < 8; ++nt) {
            const int d = nt * 8 + cpair;
            float2 e0 = *(float2*)(ex + rquad * 64 + d);
            float2 e1 = *(float2*)(ex + (rquad + 8) * 64 + d);
            *(float2*)(op0 + d) = make_float2((Ofr[nt][0] + e0.x) * inv0,
                                              (Ofr[nt][1] + e0.y) * inv0);
            *(float2*)(op1 + d) = make_float2((Ofr[nt][2] + e1.x) * inv1,
                                              (Ofr[nt][3] + e1.y) * inv1);
        }
    }
}

// =============================================================================
extern "C" void kernel_launch(void* const* d_in, const int* in_sizes, int n_in,
                              void* d_out, int out_size)
{
    const float* hs   = (const float*)d_in[0];
    const float* am   = (const float*)d_in[1];
    const float* smk  = (const float*)d_in[2];
    const float* Wq   = (const float*)d_in[3];
    const float* bq   = (const float*)d_in[4];
    const float* Wk   = (const float*)d_in[5];
    const float* bk   = (const float*)d_in[6];
    const float* Wv   = (const float*)d_in[7];
    const float* bv   = (const float*)d_in[8];
    const float* bili = (const float*)d_in[9];
    const float* absb = (const float*)d_in[10];
    float* out = (float*)d_out;

    pack_mask<<<(NSTRUCT*BB*LL*LL)/256, 256>>>(smk);
    cvt_hs<<<(BB*LL*HIDN/4)/256, 256>>>(hs);
    cvt_w<<<(3*HIDN*HIDN/4)/256, 256>>>(Wq, Wk, Wv);

    cudaFuncSetAttribute(qkv_mma_kernel, cudaFuncAttributeMaxDynamicSharedMemorySize, QT_SMEM);
    qkv_mma_kernel<<<dim3(64, 6, 3), 256, QT_SMEM>>>(bq, bk, bv);

    qb_kernel<<<dim3(128, 12, 5), 256>>>(bili);

    cudaFuncSetAttribute(attn_kernel, cudaFuncAttributeMaxDynamicSharedMemorySize, A_TOT);
    attn_kernel<<<dim3(8, 192), 256, A_TOT>>>(am, absb, out);
}

// round 15
// speedup vs baseline: 1.1164x; 1.1124x over previous
#include <cuda_runtime.h>
#include <cuda_bf16.h>
#include <math.h>
#include <cstdint>

#define BB 16
#define LL 512
#define HIDN 768
#define HH 12
#define DD 64
#define NSTRUCT 5
#define BH (BB*HH)   // 192

typedef unsigned long long ull;

// ---- packed f32x2 helpers ----
__device__ __forceinline__ void fma2(ull &d, ull a, ull b) {
    asm("fma.rn.f32x2 %0, %1, %2, %0;" : "+l"(d) : "l"(a), "l"(b));
}
__device__ __forceinline__ void mul2(ull &d, ull s) {
    asm("mul.rn.f32x2 %0, %0, %1;" : "+l"(d) : "l"(s));
}
__device__ __forceinline__ ull pack2(float lo, float hi) {
    ull r; asm("mov.b64 %0, {%1, %2};" : "=l"(r) : "f"(lo), "f"(hi)); return r;
}
__device__ __forceinline__ float2 unpack2(ull v) {
    float2 r; asm("mov.b64 {%0, %1}, %2;" : "=f"(r.x), "=f"(r.y) : "l"(v)); return r;
}

// ---- warp MMA helpers ----
__device__ __forceinline__ uint32_t smem_u32(const void* p) {
    uint32_t a;
    asm("{ .reg .u64 t; cvta.to.shared.u64 t, %1; cvt.u32.u64 %0, t; }" : "=r"(a) : "l"(p));
    return a;
}
#define LDSM4(r, addr) \
    asm volatile("ldmatrix.sync.aligned.m8n8.x4.shared.b16 {%0,%1,%2,%3}, [%4];" \
        : "=r"((r)[0]), "=r"((r)[1]), "=r"((r)[2]), "=r"((r)[3]) : "r"(addr))

__device__ __forceinline__ void mma_bf16(float* c, const uint32_t* a, const uint32_t* b) {
    asm volatile("mma.sync.aligned.m16n8k16.row.col.f32.bf16.bf16.f32 "
        "{%0,%1,%2,%3}, {%4,%5,%6,%7}, {%8,%9}, {%0,%1,%2,%3};"
        : "+f"(c[0]), "+f"(c[1]), "+f"(c[2]), "+f"(c[3])
        : "r"(a[0]), "r"(a[1]), "r"(a[2]), "r"(a[3]), "r"(b[0]), "r"(b[1]));
}
#define CP_ASYNC16(sa, gp) \
    asm volatile("cp.async.cg.shared.global [%0], [%1], 16;" :: "r"(sa), "l"(gp))
#define CP_COMMIT() asm volatile("cp.async.commit_group;" ::: "memory")
#define CP_WAIT1()  asm volatile("cp.async.wait_group 1;" ::: "memory")
#define CP_WAIT0()  asm volatile("cp.async.wait_group 0;" ::: "memory")

// ---------------- scratch ----------------
__device__ float    g_V [BH * LL * DD];            // fp32 V (PV path)
__device__ unsigned g_MB[NSTRUCT * BB * LL * (LL/32)];
__device__ __nv_bfloat16 g_hsH[BB*LL*HIDN], g_hsL[BB*LL*HIDN];
__device__ __nv_bfloat16 g_WH [3*HIDN*HIDN], g_WL [3*HIDN*HIDN];
__device__ __nv_bfloat16 g_bTH[NSTRUCT*HH*DD*DD], g_bTL[NSTRUCT*HH*DD*DD];  // bili^T split [s,h,q,p]
// pre-split bf16 operands for attention MMA
__device__ __nv_bfloat16 g_QH [BH * LL * DD], g_QL [BH * LL * DD];
__device__ __nv_bfloat16 g_KH [BH * LL * DD], g_KL [BH * LL * DD];

// =============================================================================
// Kernel 0a: pack structure mask to bits.
// =============================================================================
__global__ void __launch_bounds__(256) pack_mask(const float* __restrict__ smask)
{
    size_t e = (size_t)blockIdx.x * 256 + threadIdx.x;
    float v = smask[e];
    unsigned bal = __ballot_sync(0xffffffffu, v != 0.f);
    if ((threadIdx.x & 31) == 0) g_MB[e >> 5] = bal;
}

// =============================================================================
// split helpers + converters
// =============================================================================
__device__ __forceinline__ void split2(float a, float b, __nv_bfloat162* H, __nv_bfloat162* L) {
    __nv_bfloat16 ah = __float2bfloat16_rn(a), bh = __float2bfloat16_rn(b);
    __nv_bfloat16 al = __float2bfloat16_rn(a - __bfloat162float(ah));
    __nv_bfloat16 bl = __float2bfloat16_rn(b - __bfloat162float(bh));
    *H = __nv_bfloat162(ah, bh);
    *L = __nv_bfloat162(al, bl);
}
__global__ void __launch_bounds__(256) cvt_hs(const float* __restrict__ hs)
{
    size_t i = (size_t)blockIdx.x * 256 + threadIdx.x;
    float4 v = ((const float4*)hs)[i];
    __nv_bfloat162 h0, l0, h1, l1;
    split2(v.x, v.y, &h0, &l0);
    split2(v.z, v.w, &h1, &l1);
    ((__nv_bfloat162*)g_hsH)[2*i]   = h0;
    ((__nv_bfloat162*)g_hsH)[2*i+1] = h1;
    ((__nv_bfloat162*)g_hsL)[2*i]   = l0;
    ((__nv_bfloat162*)g_hsL)[2*i+1] = l1;
}
__global__ void __launch_bounds__(256) cvt_w(const float* __restrict__ Wq,
                                             const float* __restrict__ Wk,
                                             const float* __restrict__ Wv)
{
    size_t i = (size_t)blockIdx.x * 256 + threadIdx.x;
    const size_t per = (size_t)HIDN*HIDN/4;
    const float* src = (i < per) ? Wq : (i < 2*per) ? Wk : Wv;
    size_t loc = i % per;
    float4 v = ((const float4*)src)[loc];
    __nv_bfloat162 h0, l0, h1, l1;
    split2(v.x, v.y, &h0, &l0);
    split2(v.z, v.w, &h1, &l1);
    ((__nv_bfloat162*)g_WH)[2*i]   = h0;
    ((__nv_bfloat162*)g_WH)[2*i+1] = h1;
    ((__nv_bfloat162*)g_WL)[2*i]   = l0;
    ((__nv_bfloat162*)g_WL)[2*i+1] = l1;
}
// bili [s,h,p,q] -> transposed split [s,h,q,p]
__global__ void __launch_bounds__(256) cvt_bili(const float* __restrict__ bili)
{
    int idx = blockIdx.x * 256 + threadIdx.x;      // < 5*12*64*64
    int sh = idx >> 12;
    int pq = idx & 4095;
    int p = pq >> 6, q = pq & 63;
    float v = bili[idx];
    __nv_bfloat16 hb = __float2bfloat16_rn(v);
    __nv_bfloat16 lb = __float2bfloat16_rn(v - __bfloat162float(hb));
    size_t dst = ((size_t)sh * 64 + q) * 64 + p;
    g_bTH[dst] = hb;
    g_bTL[dst] = lb;
}

// =============================================================================
// Kernel 1: QKV projection on mma.sync bf16 (split bf16x3), R10 ordering.
// z=0 -> split g_QH/QL; z=1 -> split g_KH/KL; z=2 -> fp32 g_V.
// =============================================================================
#define QT_ROWB 80
#define QT_TILE (128 * QT_ROWB)
#define QT_STAGE (4 * QT_TILE)
#define QT_SMEM (2 * QT_STAGE)
#define NCHUNK (HIDN / 32)

__global__ void __launch_bounds__(256) qkv_mma_kernel(
    const float* __restrict__ bq, const float* __restrict__ bk, const float* __restrict__ bv)
{
    extern __shared__ __align__(16) char smem[];
    const uint32_t sb = smem_u32(smem);

    const int t = threadIdx.x, wid = t >> 5, lane = t & 31;
    const int m0 = blockIdx.x * 128;
    const int n0 = blockIdx.y * 128;
    const int z  = blockIdx.z;
    const float* bias = (z == 0) ? bq : (z == 1) ? bk : bv;
    const __nv_bfloat16* BHg = g_WH + (size_t)z * HIDN * HIDN;
    const __nv_bfloat16* BLg = g_WL + (size_t)z * HIDN * HIDN;

    const int wm = (wid & 1) * 64;
    const int wn = (wid >> 1) * 32;

    float C[4][4][4];
#pragma unroll
    for (int i = 0; i < 4; i++)
#pragma unroll
        for (int j = 0; j < 4; j++)
#pragma unroll
            for (int k = 0; k < 4; k++) C[i][j][k] = 0.f;

    const uint32_t a_off = (uint32_t)((wm + (lane & 7) + ((lane >> 3) & 1) * 8) * QT_ROWB
                                      + ((lane >> 4) * 8) * 2);
    const uint32_t b_off = (uint32_t)((wn + (lane & 7) + (lane >> 4) * 8) * QT_ROWB
                                      + (((lane >> 3) & 1) * 8) * 2);

    const int lr0 = t >> 2, lu0 = t & 3;
    const int lr1 = (t + 256) >> 2, lu1 = t & 3;

    {
        const int k0 = 0;
        uint32_t s0 = sb;
#pragma unroll
        for (int p = 0; p < 2; ++p) {
            int r = p ? lr1 : lr0, u = p ? lu1 : lu0;
            uint32_t so = (uint32_t)(r * QT_ROWB + u * 16);
            size_t ga = (size_t)(m0 + r) * HIDN + k0 + u * 8;
            size_t gb = (size_t)(n0 + r) * HIDN + k0 + u * 8;
            CP_ASYNC16(s0 + 0*QT_TILE + so, g_hsH + ga);
            CP_ASYNC16(s0 + 1*QT_TILE + so, g_hsL + ga);
            CP_ASYNC16(s0 + 2*QT_TILE + so, BHg + gb);
            CP_ASYNC16(s0 + 3*QT_TILE + so, BLg + gb);
        }
        CP_COMMIT();
    }

    for (int ch = 0; ch < NCHUNK; ++ch) {
        if (ch + 1 < NCHUNK) {
            const int k0 = (ch + 1) * 32;
            uint32_t s1 = sb + ((ch + 1) & 1) * QT_STAGE;
#pragma unroll
            for (int p = 0; p < 2; ++p) {
                int r = p ? lr1 : lr0, u = p ? lu1 : lu0;
                uint32_t so = (uint32_t)(r * QT_ROWB + u * 16);
                size_t ga = (size_t)(m0 + r) * HIDN + k0 + u * 8;
                size_t gb = (size_t)(n0 + r) * HIDN + k0 + u * 8;
                CP_ASYNC16(s1 + 0*QT_TILE + so, g_hsH + ga);
                CP_ASYNC16(s1 + 1*QT_TILE + so, g_hsL + ga);
                CP_ASYNC16(s1 + 2*QT_TILE + so, BHg + gb);
                CP_ASYNC16(s1 + 3*QT_TILE + so, BLg + gb);
            }
            CP_COMMIT();
            CP_WAIT1();
        } else {
            CP_WAIT0();
        }
        __syncthreads();

        const uint32_t st = sb + (ch & 1) * QT_STAGE;
        const uint32_t aH = st + 0*QT_TILE + a_off;
        const uint32_t aL = st + 1*QT_TILE + a_off;
        const uint32_t bHb = st + 2*QT_TILE + b_off;
        const uint32_t bLb = st + 3*QT_TILE + b_off;

#pragma unroll
        for (int ks = 0; ks < 2; ++ks) {
            const uint32_t ko = ks * 32;
            uint32_t ah[4][4], al[4][4], bh[4][2], bl[4][2];
#pragma unroll
            for (int mt = 0; mt < 4; ++mt) {
                LDSM4(ah[mt], aH + mt * 16 * QT_ROWB + ko);
                LDSM4(al[mt], aL + mt * 16 * QT_ROWB + ko);
            }
#pragma unroll
            for (int p = 0; p < 2; ++p) {
                uint32_t r4[4];
                LDSM4(r4, bHb + p * 16 * QT_ROWB + ko);
                bh[2*p][0] = r4[0]; bh[2*p][1] = r4[1];
                bh[2*p+1][0] = r4[2]; bh[2*p+1][1] = r4[3];
                LDSM4(r4, bLb + p * 16 * QT_ROWB + ko);
                bl[2*p][0] = r4[0]; bl[2*p][1] = r4[1];
                bl[2*p+1][0] = r4[2]; bl[2*p+1][1] = r4[3];
            }
#pragma unroll
            for (int mt = 0; mt < 4; ++mt)
#pragma unroll
                for (int nt = 0; nt < 4; ++nt) {
                    mma_bf16(C[mt][nt], ah[mt], bh[nt]);
                    mma_bf16(C[mt][nt], ah[mt], bl[nt]);
                    mma_bf16(C[mt][nt], al[mt], bh[nt]);
                }
        }
        __syncthreads();
    }

    // ---- epilogue ----
#pragma unroll
    for (int mt = 0; mt < 4; ++mt) {
        const int m = m0 + wm + mt * 16 + (lane >> 2);
        const int b = m >> 9, l = m & 511;
#pragma unroll
        for (int nt = 0; nt < 4; ++nt) {
            const int n = n0 + wn + nt * 8 + (lane & 3) * 2;
            const int hd = n >> 6, d = n & 63;
            const float b0 = __ldg(bias + n), b1 = __ldg(bias + n + 1);
            const size_t o1 = ((size_t)(b * HH + hd) * LL + l) * DD + d;
            const size_t o2 = ((size_t)(b * HH + hd) * LL + (l + 8)) * DD + d;
            float v00 = C[mt][nt][0] + b0, v01 = C[mt][nt][1] + b1;
            float v10 = C[mt][nt][2] + b0, v11 = C[mt][nt][3] + b1;
            if (z == 2) {
                *(float2*)(g_V + o1) = make_float2(v00, v01);
                *(float2*)(g_V + o2) = make_float2(v10, v11);
            } else {
                __nv_bfloat16* dH = (z == 0) ? g_QH : g_KH;
                __nv_bfloat16* dL = (z == 0) ? g_QL : g_KL;
                __nv_bfloat162 hh, llo;
                split2(v00, v01, &hh, &llo);
                *(__nv_bfloat162*)(dH + o1) = hh;
                *(__nv_bfloat162*)(dL + o1) = llo;
                split2(v10, v11, &hh, &llo);
                *(__nv_bfloat162*)(dH + o2) = hh;
                *(__nv_bfloat162*)(dL + o2) = llo;
            }
        }
    }
}

// =============================================================================
// Kernel 3: fused attention (R10 base), QB computed in-block via MMA.
// 32 q-rows/block, 64-wide j-tiles, 2 blocks/SM.
// =============================================================================
#define A_QH 0
#define A_QL (A_QH + 6*32*144)          // 27648
#define A_KH (A_QL + 6*32*144)          // 55296
#define A_KL (A_KH + 64*144)            // 64512
#define A_VT (A_KL + 64*144)            // 73728
#define A_SC (A_VT + 64*66*4)           // 90624
#define A_TOT (A_SC + 32*68*4)          // 99328

__device__ __forceinline__ float warp_max(float v) {
#pragma unroll
    for (int off = 16; off > 0; off >>= 1)
        v = fmaxf(v, __shfl_xor_sync(0xffffffffu, v, off));
    return v;
}
__device__ __forceinline__ float warp_sum(float v) {
#pragma unroll
    for (int off = 16; off > 0; off >>= 1)
        v += __shfl_xor_sync(0xffffffffu, v, off);
    return v;
}

__global__ void __launch_bounds__(256) attn_kernel(
    const float* __restrict__ amask,
    const float* __restrict__ absb,
    float* __restrict__ out)
{
    extern __shared__ __align__(16) char smem[];
    const uint32_t sb = smem_u32(smem);
    float* vt = (float*)(smem + A_VT);
    float* sc = (float*)(smem + A_SC);

    const int t    = threadIdx.x;
    const int w    = t >> 5;
    const int lane = t & 31;
    const int bh   = blockIdx.y;
    const int b = bh / HH, h = bh % HH;
    const int i0 = blockIdx.x * 32;

    const __nv_bfloat16* KHb = g_KH + (size_t)bh * LL * DD;
    const __nv_bfloat16* KLb = g_KL + (size_t)bh * LL * DD;
    const float* Vb = g_V + (size_t)bh * LL * DD;

    const uint32_t QLOFF = A_QL - A_QH;
    const uint32_t KLOFF = A_KL - A_KH;

    // ---- load q (component 0 only; QB computed below) ----
    for (int f = t; f < 32 * 8; f += 256) {
        int r = f >> 3, u = f & 7;
        const size_t go = (size_t)bh * LL * DD + (size_t)(i0 + r) * DD + u * 8;
        char* p = smem + r * 144 + u * 16;
        *(uint4*)(p + A_QH) = *(const uint4*)(g_QH + go);
        *(uint4*)(p + A_QL) = *(const uint4*)(g_QL + go);
    }

    // ---- compute QB_s for this block's rows into qall slots c=1..5 ----
    {
        const int wmq = (w & 1) * 16;
        const int wnq = (w >> 1) * 16;
        const uint32_t aq = sb + A_QH
            + (uint32_t)((wmq + (lane & 7) + ((lane >> 3) & 1) * 8) * 144 + (lane >> 4) * 16);
        const uint32_t bq_ = sb + A_KH
            + (uint32_t)((wnq + (lane & 7) + (lane >> 4) * 8) * 144 + ((lane >> 3) & 1) * 16);
        for (int s = 0; s < NSTRUCT; ++s) {
            __syncthreads();   // q-load / previous staging readers done
            const size_t boff = (size_t)(s * HH + h) * 64 * 64;
            for (int f = t; f < 512; f += 256) {
                int r = f >> 3, u = f & 7;
                char* p = smem + r * 144 + u * 16;
                *(uint4*)(p + A_KH) = *(const uint4*)(g_bTH + boff + (size_t)r * 64 + u * 8);
                *(uint4*)(p + A_KL) = *(const uint4*)(g_bTL + boff + (size_t)r * 64 + u * 8);
            }
            __syncthreads();

            float C[2][4];
#pragma unroll
            for (int nt = 0; nt < 2; ++nt)
#pragma unroll
                for (int k = 0; k < 4; ++k) C[nt][k] = 0.f;
#pragma unroll
            for (int ks = 0; ks < 4; ++ks) {
                const uint32_t ko = ks * 32;
                uint32_t ah[4], al[4], bhf[2][2], blf[2][2];
                LDSM4(ah, aq + ko);
                LDSM4(al, aq + QLOFF + ko);
                {
                    uint32_t r4[4];
                    LDSM4(r4, bq_ + ko);
                    bhf[0][0] = r4[0]; bhf[0][1] = r4[1];
                    bhf[1][0] = r4[2]; bhf[1][1] = r4[3];
                    LDSM4(r4, bq_ + KLOFF + ko);
                    blf[0][0] = r4[0]; blf[0][1] = r4[1];
                    blf[1][0] = r4[2]; blf[1][1] = r4[3];
                }
#pragma unroll
                for (int nt = 0; nt < 2; ++nt) {
                    mma_bf16(C[nt], ah, bhf[nt]);
                    mma_bf16(C[nt], ah, blf[nt]);
                    mma_bf16(C[nt], al, bhf[nt]);
                }
            }
            // store split QB into qall slot c=s+1
            const int r0 = wmq + (lane >> 2);
#pragma unroll
            for (int nt = 0; nt < 2; ++nt) {
                const int col = wnq + nt * 8 + (lane & 3) * 2;
                __nv_bfloat162 hh, llo;
                split2(C[nt][0], C[nt][1], &hh, &llo);
                *(__nv_bfloat162*)(smem + A_QH + ((s+1)*32 + r0) * 144 + col * 2) = hh;
                *(__nv_bfloat162*)(smem + A_QL + ((s+1)*32 + r0) * 144 + col * 2) = llo;
                split2(C[nt][2], C[nt][3], &hh, &llo);
                *(__nv_bfloat162*)(smem + A_QH + ((s+1)*32 + r0 + 8) * 144 + col * 2) = hh;
                *(__nv_bfloat162*)(smem + A_QL + ((s+1)*32 + r0 + 8) * 144 + col * 2) = llo;
            }
        }
    }

    float ab[NSTRUCT];
#pragma unroll
    for (int s = 0; s < NSTRUCT; ++s) ab[s] = __ldg(absb + s*HH + h);

    float mrow[4], lrow[4];
    ull ctx2[4][2];
#pragma unroll
    for (int i = 0; i < 4; ++i) {
        mrow[i] = -1e30f; lrow[i] = 0.f;
        ctx2[i][0] = 0ULL; ctx2[i][1] = 0ULL;
    }

    const int row0 = w * 4;
    const int wm = (w & 1) * 16;
    const int wn = (w >> 1) * 16;

    const uint32_t a_base = sb + A_QH
        + (uint32_t)((wm + (lane & 7) + ((lane >> 3) & 1) * 8) * 144 + (lane >> 4) * 16);
    const uint32_t b_base = sb + A_KH
        + (uint32_t)((wn + (lane & 7) + (lane >> 4) * 8) * 144 + ((lane >> 3) & 1) * 16);

    const int widx_base = (wn >> 5);
    const int bp0 = (wn & 31) + (lane & 3) * 2;

    for (int jt = 0; jt < 8; ++jt) {
        const int j0 = jt * 64;
        __syncthreads();
        // ---- load K tile (pre-split bf16) ----
        for (int f = t; f < 64 * 8; f += 256) {
            int j = f >> 3, u = f & 7;
            const size_t go = (size_t)(j0 + j) * DD + u * 8;
            char* p = smem + j * 144 + u * 16;
            *(uint4*)(p + A_KH) = *(const uint4*)(KHb + go);
            *(uint4*)(p + A_KL) = *(const uint4*)(KLb + go);
        }
        // ---- load V tile (fp32, transposed [d][j]) ----
        for (int f = t; f < 1024; f += 256) {
            int j = f >> 4, dv = f & 15;
            float4 v4 = *(const float4*)(Vb + (size_t)(j0 + j) * DD + dv * 4);
            vt[(dv*4+0)*66 + j] = v4.x;
            vt[(dv*4+1)*66 + j] = v4.y;
            vt[(dv*4+2)*66 + j] = v4.z;
            vt[(dv*4+3)*66 + j] = v4.w;
        }
        __syncthreads();

        // ---- MMA: S fragment [2 nt][4] ----
        float S[2][4];
#pragma unroll
        for (int j = 0; j < 2; ++j)
#pragma unroll
            for (int k = 0; k < 4; ++k) S[j][k] = 0.f;

        for (int c = 0; c < 6; ++c) {
            float Sc[2][4];
            float (*acc)[4] = (c == 0) ? S : Sc;
            if (c != 0) {
#pragma unroll
                for (int j = 0; j < 2; ++j)
#pragma unroll
                    for (int k = 0; k < 4; ++k) Sc[j][k] = 0.f;
            }
            const uint32_t aH = a_base + (uint32_t)(c * 32 * 144);
#pragma unroll
            for (int ks = 0; ks < 4; ++ks) {
                const uint32_t ko = ks * 32;
                uint32_t ah[4], al[4], bhf[2][2], blf[2][2];
                LDSM4(ah, aH + ko);
                LDSM4(al, aH + QLOFF + ko);
                {
                    uint32_t r4[4];
                    LDSM4(r4, b_base + ko);
                    bhf[0][0] = r4[0]; bhf[0][1] = r4[1];
                    bhf[1][0] = r4[2]; bhf[1][1] = r4[3];
                    LDSM4(r4, b_base + KLOFF + ko);
                    blf[0][0] = r4[0]; blf[0][1] = r4[1];
                    blf[1][0] = r4[2]; blf[1][1] = r4[3];
                }
#pragma unroll
                for (int nt = 0; nt < 2; ++nt) {
                    mma_bf16(acc[nt], ah, bhf[nt]);
                    mma_bf16(acc[nt], ah, blf[nt]);
                    mma_bf16(acc[nt], al, bhf[nt]);
                }
            }
            if (c != 0) {
                const int s = c - 1;
                const float abs_s = ab[s];
                const size_t mrowbase = ((size_t)(s*BB + b) * LL + i0 + wm) * 16;
                const int rloc = lane >> 2;
                const size_t wi = (size_t)(jt * 2 + widx_base);
                unsigned mw0 = g_MB[mrowbase + (size_t)rloc * 16 + wi];
                unsigned mw1 = g_MB[mrowbase + (size_t)(rloc + 8) * 16 + wi];
#pragma unroll
                for (int nt = 0; nt < 2; ++nt) {
                    const int bp = bp0 + nt * 8;
                    S[nt][0] += (float)((mw0 >> bp) & 1u)     * (Sc[nt][0] + abs_s);
                    S[nt][1] += (float)((mw0 >> (bp+1)) & 1u) * (Sc[nt][1] + abs_s);
                    S[nt][2] += (float)((mw1 >> bp) & 1u)     * (Sc[nt][2] + abs_s);
                    S[nt][3] += (float)((mw1 >> (bp+1)) & 1u) * (Sc[nt][3] + abs_s);
                }
            }
        }

        // ---- spill S fragments to sc ----
        {
            const int rr = wm + (lane >> 2);
#pragma unroll
            for (int nt = 0; nt < 2; ++nt) {
                const int cc = wn + nt * 8 + (lane & 3) * 2;
                *(float2*)&sc[rr * 68 + cc]       = make_float2(S[nt][0], S[nt][1]);
                *(float2*)&sc[(rr + 8) * 68 + cc] = make_float2(S[nt][2], S[nt][3]);
            }
        }
        __syncthreads();

        // ---- online softmax (warp owns rows row0..row0+3) ----
        float amv[2];
        amv[0] = __ldg(amask + (size_t)b * LL + j0 + lane);
        amv[1] = __ldg(amask + (size_t)b * LL + j0 + lane + 32);

#pragma unroll
        for (int ii = 0; ii < 4; ++ii) {
            const int r = row0 + ii;
            float lg0 = sc[r * 68 + lane]      * 0.125f + amv[0];
            float lg1 = sc[r * 68 + lane + 32] * 0.125f + amv[1];
            float mt = warp_max(fmaxf(lg0, lg1));
            float mnew = fmaxf(mrow[ii], mt);
            float corr = __expf(mrow[ii] - mnew);
            mrow[ii] = mnew;
            float p0 = __expf(lg0 - mnew);
            float p1 = __expf(lg1 - mnew);
            sc[r * 68 + lane]      = p0;
            sc[r * 68 + lane + 32] = p1;
            float psum = warp_sum(p0 + p1);
            lrow[ii] = lrow[ii] * corr + psum;
            ull c2 = pack2(corr, corr);
            mul2(ctx2[ii][0], c2);
            mul2(ctx2[ii][1], c2);
        }
        __syncwarp();

        // ---- PV (FFMA2): vt [d][j=64] ----
        const float* vr0 = &vt[lane * 66];
        const float* vr1 = &vt[(lane + 32) * 66];
#pragma unroll 4
        for (int j2 = 0; j2 < 32; ++j2) {
            ull vv0 = *(const ull*)(vr0 + 2*j2);
            ull vv1 = *(const ull*)(vr1 + 2*j2);
#pragma unroll
            for (int ii = 0; ii < 4; ++ii) {
                ull pp = *(const ull*)&sc[(row0 + ii) * 68 + 2*j2];
                fma2(ctx2[ii][0], pp, vv0);
                fma2(ctx2[ii][1], pp, vv1);
            }
        }
    }

    // ---- finalize ----
#pragma unroll
    for (int ii = 0; ii < 4; ++ii) {
        const int ig = i0 + row0 + ii;
        float inv = 1.f / lrow[ii];
        float* op = out + (size_t)(b * LL + ig) * (HH*DD) + h * DD;
        float2 c0 = unpack2(ctx2[ii][0]);
        float2 c1 = unpack2(ctx2[ii][1]);
        op[lane]      = (c0.x + c0.y) * inv;
        op[lane + 32] = (c1.x + c1.y) * inv;
    }
}

// =============================================================================
extern "C" void kernel_launch(void* const* d_in, const int* in_sizes, int n_in,
                              void* d_out, int out_size)
{
    const float* hs   = (const float*)d_in[0];
    const float* am   = (const float*)d_in[1];
    const float* smk  = (const float*)d_in[2];
    const float* Wq   = (const float*)d_in[3];
    const float* bq   = (const float*)d_in[4];
    const float* Wk   = (const float*)d_in[5];
    const float* bk   = (const float*)d_in[6];
    const float* Wv   = (const float*)d_in[7];
    const float* bv   = (const float*)d_in[8];
    const float* bili = (const float*)d_in[9];
    const float* absb = (const float*)d_in[10];
    float* out = (float*)d_out;

    pack_mask<<<(NSTRUCT*BB*LL*LL)/256, 256>>>(smk);
    cvt_hs<<<(BB*LL*HIDN/4)/256, 256>>>(hs);
    cvt_w<<<(3*HIDN*HIDN/4)/256, 256>>>(Wq, Wk, Wv);
    cvt_bili<<<(NSTRUCT*HH*DD*DD)/256, 256>>>(bili);

    cudaFuncSetAttribute(qkv_mma_kernel, cudaFuncAttributeMaxDynamicSharedMemorySize, QT_SMEM);
    qkv_mma_kernel<<<dim3(64, 6, 3), 256, QT_SMEM>>>(bq, bk, bv);

    cudaFuncSetAttribute(attn_kernel, cudaFuncAttributeMaxDynamicSharedMemorySize, A_TOT);
    attn_kernel<<<dim3(16, 192), 256, A_TOT>>>(am, absb, out);
}

// round 16
// speedup vs baseline: 1.2810x; 1.1474x over previous
#include <cuda_runtime.h>
#include <cuda_bf16.h>
#include <math.h>
#include <cstdint>

#define BB 16
#define LL 512
#define HIDN 768
#define HH 12
#define DD 64
#define NSTRUCT 5
#define BH (BB*HH)   // 192

// ---- warp MMA helpers ----
__device__ __forceinline__ uint32_t smem_u32(const void* p) {
    uint32_t a;
    asm("{ .reg .u64 t; cvta.to.shared.u64 t, %1; cvt.u32.u64 %0, t; }" : "=r"(a) : "l"(p));
    return a;
}
#define LDSM4(r, addr) \
    asm volatile("ldmatrix.sync.aligned.m8n8.x4.shared.b16 {%0,%1,%2,%3}, [%4];" \
        : "=r"((r)[0]), "=r"((r)[1]), "=r"((r)[2]), "=r"((r)[3]) : "r"(addr))

__device__ __forceinline__ void mma_bf16(float* c, const uint32_t* a, const uint32_t* b) {
    asm volatile("mma.sync.aligned.m16n8k16.row.col.f32.bf16.bf16.f32 "
        "{%0,%1,%2,%3}, {%4,%5,%6,%7}, {%8,%9}, {%0,%1,%2,%3};"
        : "+f"(c[0]), "+f"(c[1]), "+f"(c[2]), "+f"(c[3])
        : "r"(a[0]), "r"(a[1]), "r"(a[2]), "r"(a[3]), "r"(b[0]), "r"(b[1]));
}
#define CP_ASYNC16(sa, gp) \
    asm volatile("cp.async.cg.shared.global [%0], [%1], 16;" :: "r"(sa), "l"(gp))
#define CP_COMMIT() asm volatile("cp.async.commit_group;" ::: "memory")
#define CP_WAIT1()  asm volatile("cp.async.wait_group 1;" ::: "memory")
#define CP_WAIT0()  asm volatile("cp.async.wait_group 0;" ::: "memory")

// ---------------- scratch ----------------
__device__ unsigned g_MB[NSTRUCT * BB * LL * (LL/32)];
__device__ __nv_bfloat16 g_hsH[BB*LL*HIDN], g_hsL[BB*LL*HIDN];
__device__ __nv_bfloat16 g_WH [3*HIDN*HIDN], g_WL [3*HIDN*HIDN];
__device__ __nv_bfloat16 g_bTH[NSTRUCT*HH*DD*DD], g_bTL[NSTRUCT*HH*DD*DD];
__device__ __nv_bfloat16 g_QH [BH * LL * DD], g_QL [BH * LL * DD];
__device__ __nv_bfloat16 g_KH [BH * LL * DD], g_KL [BH * LL * DD];
__device__ __nv_bfloat16 g_VTH[BH * DD * LL], g_VTL[BH * DD * LL];   // V^T split [bh][d][l]

// =============================================================================
// Kernel 0a: pack structure mask to bits.
// =============================================================================
__global__ void __launch_bounds__(256) pack_mask(const float* __restrict__ smask)
{
    size_t e = (size_t)blockIdx.x * 256 + threadIdx.x;
    float v = smask[e];
    unsigned bal = __ballot_sync(0xffffffffu, v != 0.f);
    if ((threadIdx.x & 31) == 0) g_MB[e >> 5] = bal;
}

// =============================================================================
// split helpers + converters
// =============================================================================
__device__ __forceinline__ void split2(float a, float b, __nv_bfloat162* H, __nv_bfloat162* L) {
    __nv_bfloat16 ah = __float2bfloat16_rn(a), bh = __float2bfloat16_rn(b);
    __nv_bfloat16 al = __float2bfloat16_rn(a - __bfloat162float(ah));
    __nv_bfloat16 bl = __float2bfloat16_rn(b - __bfloat162float(bh));
    *H = __nv_bfloat162(ah, bh);
    *L = __nv_bfloat162(al, bl);
}
__global__ void __launch_bounds__(256) cvt_hs(const float* __restrict__ hs)
{
    size_t i = (size_t)blockIdx.x * 256 + threadIdx.x;
    float4 v = ((const float4*)hs)[i];
    __nv_bfloat162 h0, l0, h1, l1;
    split2(v.x, v.y, &h0, &l0);
    split2(v.z, v.w, &h1, &l1);
    ((__nv_bfloat162*)g_hsH)[2*i]   = h0;
    ((__nv_bfloat162*)g_hsH)[2*i+1] = h1;
    ((__nv_bfloat162*)g_hsL)[2*i]   = l0;
    ((__nv_bfloat162*)g_hsL)[2*i+1] = l1;
}
__global__ void __launch_bounds__(256) cvt_w(const float* __restrict__ Wq,
                                             const float* __restrict__ Wk,
                                             const float* __restrict__ Wv)
{
    size_t i = (size_t)blockIdx.x * 256 + threadIdx.x;
    const size_t per = (size_t)HIDN*HIDN/4;
    const float* src = (i < per) ? Wq : (i < 2*per) ? Wk : Wv;
    size_t loc = i % per;
    float4 v = ((const float4*)src)[loc];
    __nv_bfloat162 h0, l0, h1, l1;
    split2(v.x, v.y, &h0, &l0);
    split2(v.z, v.w, &h1, &l1);
    ((__nv_bfloat162*)g_WH)[2*i]   = h0;
    ((__nv_bfloat162*)g_WH)[2*i+1] = h1;
    ((__nv_bfloat162*)g_WL)[2*i]   = l0;
    ((__nv_bfloat162*)g_WL)[2*i+1] = l1;
}
__global__ void __launch_bounds__(256) cvt_bili(const float* __restrict__ bili)
{
    int idx = blockIdx.x * 256 + threadIdx.x;
    int sh = idx >> 12;
    int pq = idx & 4095;
    int p = pq >> 6, q = pq & 63;
    float v = bili[idx];
    __nv_bfloat16 hb = __float2bfloat16_rn(v);
    __nv_bfloat16 lb = __float2bfloat16_rn(v - __bfloat162float(hb));
    size_t dst = ((size_t)sh * 64 + q) * 64 + p;
    g_bTH[dst] = hb;
    g_bTL[dst] = lb;
}

// =============================================================================
// Kernel 1: QKV projection on mma.sync bf16 (split bf16x3).
// z=0 -> split g_QH/QL; z=1 -> split g_KH/KL; z=2 -> split V^T g_VTH/VTL.
// =============================================================================
#define QT_ROWB 80
#define QT_TILE (128 * QT_ROWB)
#define QT_STAGE (4 * QT_TILE)
#define QT_SMEM (2 * QT_STAGE)
#define NCHUNK (HIDN / 32)

__global__ void __launch_bounds__(256) qkv_mma_kernel(
    const float* __restrict__ bq, const float* __restrict__ bk, const float* __restrict__ bv)
{
    extern __shared__ __align__(16) char smem[];
    const uint32_t sb = smem_u32(smem);

    const int t = threadIdx.x, wid = t >> 5, lane = t & 31;
    const int m0 = blockIdx.x * 128;
    const int n0 = blockIdx.y * 128;
    const int z  = blockIdx.z;
    const float* bias = (z == 0) ? bq : (z == 1) ? bk : bv;
    const __nv_bfloat16* BHg = g_WH + (size_t)z * HIDN * HIDN;
    const __nv_bfloat16* BLg = g_WL + (size_t)z * HIDN * HIDN;

    const int wm = (wid & 1) * 64;
    const int wn = (wid >> 1) * 32;

    float C[4][4][4];
#pragma unroll
    for (int i = 0; i < 4; i++)
#pragma unroll
        for (int j = 0; j < 4; j++)
#pragma unroll
            for (int k = 0; k < 4; k++) C[i][j][k] = 0.f;

    const uint32_t a_off = (uint32_t)((wm + (lane & 7) + ((lane >> 3) & 1) * 8) * QT_ROWB
                                      + ((lane >> 4) * 8) * 2);
    const uint32_t b_off = (uint32_t)((wn + (lane & 7) + (lane >> 4) * 8) * QT_ROWB
                                      + (((lane >> 3) & 1) * 8) * 2);

    const int lr0 = t >> 2, lu0 = t & 3;
    const int lr1 = (t + 256) >> 2, lu1 = t & 3;

    {
        const int k0 = 0;
        uint32_t s0 = sb;
#pragma unroll
        for (int p = 0; p < 2; ++p) {
            int r = p ? lr1 : lr0, u = p ? lu1 : lu0;
            uint32_t so = (uint32_t)(r * QT_ROWB + u * 16);
            size_t ga = (size_t)(m0 + r) * HIDN + k0 + u * 8;
            size_t gb = (size_t)(n0 + r) * HIDN + k0 + u * 8;
            CP_ASYNC16(s0 + 0*QT_TILE + so, g_hsH + ga);
            CP_ASYNC16(s0 + 1*QT_TILE + so, g_hsL + ga);
            CP_ASYNC16(s0 + 2*QT_TILE + so, BHg + gb);
            CP_ASYNC16(s0 + 3*QT_TILE + so, BLg + gb);
        }
        CP_COMMIT();
    }

    for (int ch = 0; ch < NCHUNK; ++ch) {
        if (ch + 1 < NCHUNK) {
            const int k0 = (ch + 1) * 32;
            uint32_t s1 = sb + ((ch + 1) & 1) * QT_STAGE;
#pragma unroll
            for (int p = 0; p < 2; ++p) {
                int r = p ? lr1 : lr0, u = p ? lu1 : lu0;
                uint32_t so = (uint32_t)(r * QT_ROWB + u * 16);
                size_t ga = (size_t)(m0 + r) * HIDN + k0 + u * 8;
                size_t gb = (size_t)(n0 + r) * HIDN + k0 + u * 8;
                CP_ASYNC16(s1 + 0*QT_TILE + so, g_hsH + ga);
                CP_ASYNC16(s1 + 1*QT_TILE + so, g_hsL + ga);
                CP_ASYNC16(s1 + 2*QT_TILE + so, BHg + gb);
                CP_ASYNC16(s1 + 3*QT_TILE + so, BLg + gb);
            }
            CP_COMMIT();
            CP_WAIT1();
        } else {
            CP_WAIT0();
        }
        __syncthreads();

        const uint32_t st = sb + (ch & 1) * QT_STAGE;
        const uint32_t aH = st + 0*QT_TILE + a_off;
        const uint32_t aL = st + 1*QT_TILE + a_off;
        const uint32_t bHb = st + 2*QT_TILE + b_off;
        const uint32_t bLb = st + 3*QT_TILE + b_off;

#pragma unroll
        for (int ks = 0; ks < 2; ++ks) {
            const uint32_t ko = ks * 32;
            uint32_t ah[4][4], al[4][4], bh[4][2], bl[4][2];
#pragma unroll
            for (int mt = 0; mt < 4; ++mt) {
                LDSM4(ah[mt], aH + mt * 16 * QT_ROWB + ko);
                LDSM4(al[mt], aL + mt * 16 * QT_ROWB + ko);
            }
#pragma unroll
            for (int p = 0; p < 2; ++p) {
                uint32_t r4[4];
                LDSM4(r4, bHb + p * 16 * QT_ROWB + ko);
                bh[2*p][0] = r4[0]; bh[2*p][1] = r4[1];
                bh[2*p+1][0] = r4[2]; bh[2*p+1][1] = r4[3];
                LDSM4(r4, bLb + p * 16 * QT_ROWB + ko);
                bl[2*p][0] = r4[0]; bl[2*p][1] = r4[1];
                bl[2*p+1][0] = r4[2]; bl[2*p+1][1] = r4[3];
            }
#pragma unroll
            for (int mt = 0; mt < 4; ++mt)
#pragma unroll
                for (int nt = 0; nt < 4; ++nt) {
                    mma_bf16(C[mt][nt], ah[mt], bh[nt]);
                    mma_bf16(C[mt][nt], ah[mt], bl[nt]);
                    mma_bf16(C[mt][nt], al[mt], bh[nt]);
                }
        }
        __syncthreads();
    }

    // ---- epilogue ----
#pragma unroll
    for (int mt = 0; mt < 4; ++mt) {
        const int m = m0 + wm + mt * 16 + (lane >> 2);
        const int b = m >> 9, l = m & 511;
#pragma unroll
        for (int nt = 0; nt < 4; ++nt) {
            const int n = n0 + wn + nt * 8 + (lane & 3) * 2;
            const int hd = n >> 6, d = n & 63;
            const float b0 = __ldg(bias + n), b1 = __ldg(bias + n + 1);
            float v00 = C[mt][nt][0] + b0, v01 = C[mt][nt][1] + b1;
            float v10 = C[mt][nt][2] + b0, v11 = C[mt][nt][3] + b1;
            if (z == 2) {
                const size_t vb = (size_t)(b * HH + hd) * DD;
                __nv_bfloat16 h00 = __float2bfloat16_rn(v00);
                __nv_bfloat16 h01 = __float2bfloat16_rn(v01);
                __nv_bfloat16 h10 = __float2bfloat16_rn(v10);
                __nv_bfloat16 h11 = __float2bfloat16_rn(v11);
                g_VTH[(vb + d)     * LL + l]     = h00;
                g_VTH[(vb + d + 1) * LL + l]     = h01;
                g_VTH[(vb + d)     * LL + l + 8] = h10;
                g_VTH[(vb + d + 1) * LL + l + 8] = h11;
                g_VTL[(vb + d)     * LL + l]     = __float2bfloat16_rn(v00 - __bfloat162float(h00));
                g_VTL[(vb + d + 1) * LL + l]     = __float2bfloat16_rn(v01 - __bfloat162float(h01));
                g_VTL[(vb + d)     * LL + l + 8] = __float2bfloat16_rn(v10 - __bfloat162float(h10));
                g_VTL[(vb + d + 1) * LL + l + 8] = __float2bfloat16_rn(v11 - __bfloat162float(h11));
            } else {
                const size_t o1 = ((size_t)(b * HH + hd) * LL + l) * DD + d;
                const size_t o2 = ((size_t)(b * HH + hd) * LL + (l + 8)) * DD + d;
                __nv_bfloat16* dH = (z == 0) ? g_QH : g_KH;
                __nv_bfloat16* dL = (z == 0) ? g_QL : g_KL;
                __nv_bfloat162 hh, llo;
                split2(v00, v01, &hh, &llo);
                *(__nv_bfloat162*)(dH + o1) = hh;
                *(__nv_bfloat162*)(dL + o1) = llo;
                split2(v10, v11, &hh, &llo);
                *(__nv_bfloat162*)(dH + o2) = hh;
                *(__nv_bfloat162*)(dL + o2) = llo;
            }
        }
    }
}

// =============================================================================
// Kernel 3: fused attention, QB fused, PV via MMA (P split bf16).
// 32 q-rows/block, 64-wide j-tiles, 2 blocks/SM.
// =============================================================================
#define A_QH 0
#define A_QL (A_QH + 6*32*144)        // 27648
#define A_KH (A_QL + 6*32*144)        // 55296
#define A_KL (A_KH + 64*144)          // 64512
#define A_VH (A_KL + 64*144)          // 73728
#define A_VL (A_VH + 64*144)          // 82944
#define A_SC (A_VL + 64*144)          // 92160  (fp32 32x68)
#define A_PH (A_SC + 32*68*4)         // 100864
#define A_PL (A_PH + 32*144)          // 105472
#define A_CR (A_PL + 32*144)          // 110080 (corr[32])
#define A_LR (A_CR + 128)             // 110208 (lrow[32])
#define A_TOT (A_LR + 128)            // 110336

__device__ __forceinline__ float warp_max(float v) {
#pragma unroll
    for (int off = 16; off > 0; off >>= 1)
        v = fmaxf(v, __shfl_xor_sync(0xffffffffu, v, off));
    return v;
}
__device__ __forceinline__ float warp_sum(float v) {
#pragma unroll
    for (int off = 16; off > 0; off >>= 1)
        v += __shfl_xor_sync(0xffffffffu, v, off);
    return v;
}

__global__ void __launch_bounds__(256) attn_kernel(
    const float* __restrict__ amask,
    const float* __restrict__ absb,
    float* __restrict__ out)
{
    extern __shared__ __align__(16) char smem[];
    const uint32_t sb = smem_u32(smem);
    float* sc  = (float*)(smem + A_SC);
    float* crp = (float*)(smem + A_CR);
    float* lrp = (float*)(smem + A_LR);

    const int t    = threadIdx.x;
    const int w    = t >> 5;
    const int lane = t & 31;
    const int bh   = blockIdx.y;
    const int b = bh / HH, h = bh % HH;
    const int i0 = blockIdx.x * 32;

    const __nv_bfloat16* KHb = g_KH + (size_t)bh * LL * DD;
    const __nv_bfloat16* KLb = g_KL + (size_t)bh * LL * DD;
    const __nv_bfloat16* VHb = g_VTH + (size_t)bh * DD * LL;
    const __nv_bfloat16* VLb = g_VTL + (size_t)bh * DD * LL;

    const uint32_t QLOFF = A_QL - A_QH;
    const uint32_t KLOFF = A_KL - A_KH;
    const uint32_t VLOFF = A_VL - A_VH;
    const uint32_t PLOFF = A_PL - A_PH;

    // ---- load q (component 0) ----
    for (int f = t; f < 32 * 8; f += 256) {
        int r = f >> 3, u = f & 7;
        const size_t go = (size_t)bh * LL * DD + (size_t)(i0 + r) * DD + u * 8;
        char* p = smem + r * 144 + u * 16;
        *(uint4*)(p + A_QH) = *(const uint4*)(g_QH + go);
        *(uint4*)(p + A_QL) = *(const uint4*)(g_QL + go);
    }

    // ---- compute QB_s into qall slots c=1..5 ----
    {
        const int wmq = (w & 1) * 16;
        const int wnq = (w >> 1) * 16;
        const uint32_t aq = sb + A_QH
            + (uint32_t)((wmq + (lane & 7) + ((lane >> 3) & 1) * 8) * 144 + (lane >> 4) * 16);
        const uint32_t bq_ = sb + A_KH
            + (uint32_t)((wnq + (lane & 7) + (lane >> 4) * 8) * 144 + ((lane >> 3) & 1) * 16);
        for (int s = 0; s < NSTRUCT; ++s) {
            __syncthreads();
            const size_t boff = (size_t)(s * HH + h) * 64 * 64;
            for (int f = t; f < 512; f += 256) {
                int r = f >> 3, u = f & 7;
                char* p = smem + r * 144 + u * 16;
                *(uint4*)(p + A_KH) = *(const uint4*)(g_bTH + boff + (size_t)r * 64 + u * 8);
                *(uint4*)(p + A_KL) = *(const uint4*)(g_bTL + boff + (size_t)r * 64 + u * 8);
            }
            __syncthreads();

            float C[2][4];
#pragma unroll
            for (int nt = 0; nt < 2; ++nt)
#pragma unroll
                for (int k = 0; k < 4; ++k) C[nt][k] = 0.f;
#pragma unroll
            for (int ks = 0; ks < 4; ++ks) {
                const uint32_t ko = ks * 32;
                uint32_t ah[4], al[4], bhf[2][2], blf[2][2];
                LDSM4(ah, aq + ko);
                LDSM4(al, aq + QLOFF + ko);
                {
                    uint32_t r4[4];
                    LDSM4(r4, bq_ + ko);
                    bhf[0][0] = r4[0]; bhf[0][1] = r4[1];
                    bhf[1][0] = r4[2]; bhf[1][1] = r4[3];
                    LDSM4(r4, bq_ + KLOFF + ko);
                    blf[0][0] = r4[0]; blf[0][1] = r4[1];
                    blf[1][0] = r4[2]; blf[1][1] = r4[3];
                }
#pragma unroll
                for (int nt = 0; nt < 2; ++nt) {
                    mma_bf16(C[nt], ah, bhf[nt]);
                    mma_bf16(C[nt], ah, blf[nt]);
                    mma_bf16(C[nt], al, bhf[nt]);
                }
            }
            const int r0 = wmq + (lane >> 2);
#pragma unroll
            for (int nt = 0; nt < 2; ++nt) {
                const int col = wnq + nt * 8 + (lane & 3) * 2;
                __nv_bfloat162 hh, llo;
                split2(C[nt][0], C[nt][1], &hh, &llo);
                *(__nv_bfloat162*)(smem + A_QH + ((s+1)*32 + r0) * 144 + col * 2) = hh;
                *(__nv_bfloat162*)(smem + A_QL + ((s+1)*32 + r0) * 144 + col * 2) = llo;
                split2(C[nt][2], C[nt][3], &hh, &llo);
                *(__nv_bfloat162*)(smem + A_QH + ((s+1)*32 + r0 + 8) * 144 + col * 2) = hh;
                *(__nv_bfloat162*)(smem + A_QL + ((s+1)*32 + r0 + 8) * 144 + col * 2) = llo;
            }
        }
    }

    float ab[NSTRUCT];
#pragma unroll
    for (int s = 0; s < NSTRUCT; ++s) ab[s] = __ldg(absb + s*HH + h);

    float mrow[4], lrow[4];
#pragma unroll
    for (int i = 0; i < 4; ++i) { mrow[i] = -1e30f; lrow[i] = 0.f; }

    const int row0 = w * 4;          // softmax ownership
    const int wm = (w & 1) * 16;     // S-mma m offset / PV P-row group
    const int wn = (w >> 1) * 16;    // S-mma n offset
    const int d0 = (w >> 1) * 16;    // PV output d-cols

    float Ofr[2][4];                 // PV fragment: rows wm+rquad(+8), cols d0+nt*8+..
#pragma unroll
    for (int nt = 0; nt < 2; ++nt)
#pragma unroll
        for (int k = 0; k < 4; ++k) Ofr[nt][k] = 0.f;

    const uint32_t a_base = sb + A_QH
        + (uint32_t)((wm + (lane & 7) + ((lane >> 3) & 1) * 8) * 144 + (lane >> 4) * 16);
    const uint32_t b_base = sb + A_KH
        + (uint32_t)((wn + (lane & 7) + (lane >> 4) * 8) * 144 + ((lane >> 3) & 1) * 16);
    const uint32_t a_pv = sb + A_PH
        + (uint32_t)((wm + (lane & 7) + ((lane >> 3) & 1) * 8) * 144 + (lane >> 4) * 16);
    const uint32_t b_pv = sb + A_VH
        + (uint32_t)((d0 + (lane & 7) + (lane >> 4) * 8) * 144 + ((lane >> 3) & 1) * 16);

    const int widx_base = (wn >> 5);
    const int bp0 = (wn & 31) + (lane & 3) * 2;
    const int rquad = lane >> 2;

    for (int jt = 0; jt < 8; ++jt) {
        const int j0 = jt * 64;
        __syncthreads();
        // ---- load K tile (split) ----
        for (int f = t; f < 64 * 8; f += 256) {
            int j = f >> 3, u = f & 7;
            const size_t go = (size_t)(j0 + j) * DD + u * 8;
            char* p = smem + j * 144 + u * 16;
            *(uint4*)(p + A_KH) = *(const uint4*)(KHb + go);
            *(uint4*)(p + A_KL) = *(const uint4*)(KLb + go);
        }
        // ---- load V^T tile (split): 64 d-rows x 64 j ----
        for (int f = t; f < 64 * 4; f += 256) {
            int d = f >> 2, u = f & 3;
            const size_t go = (size_t)d * LL + j0 + u * 16;
            char* p = smem + d * 144 + u * 32;
            *(uint4*)(p + A_VH)      = *(const uint4*)(VHb + go);
            *(uint4*)(p + A_VH + 16) = *(const uint4*)(VHb + go + 8);
            *(uint4*)(p + A_VL)      = *(const uint4*)(VLb + go);
            *(uint4*)(p + A_VL + 16) = *(const uint4*)(VLb + go + 8);
        }
        __syncthreads();

        // ---- S MMA: 6 components ----
        float S[2][4];
#pragma unroll
        for (int j = 0; j < 2; ++j)
#pragma unroll
            for (int k = 0; k < 4; ++k) S[j][k] = 0.f;

        for (int c = 0; c < 6; ++c) {
            float Sc[2][4];
            float (*acc)[4] = (c == 0) ? S : Sc;
            if (c != 0) {
#pragma unroll
                for (int j = 0; j < 2; ++j)
#pragma unroll
                    for (int k = 0; k < 4; ++k) Sc[j][k] = 0.f;
            }
            const uint32_t aH = a_base + (uint32_t)(c * 32 * 144);
#pragma unroll
            for (int ks = 0; ks < 4; ++ks) {
                const uint32_t ko = ks * 32;
                uint32_t ah[4], al[4], bhf[2][2], blf[2][2];
                LDSM4(ah, aH + ko);
                LDSM4(al, aH + QLOFF + ko);
                {
                    uint32_t r4[4];
                    LDSM4(r4, b_base + ko);
                    bhf[0][0] = r4[0]; bhf[0][1] = r4[1];
                    bhf[1][0] = r4[2]; bhf[1][1] = r4[3];
                    LDSM4(r4, b_base + KLOFF + ko);
                    blf[0][0] = r4[0]; blf[0][1] = r4[1];
                    blf[1][0] = r4[2]; blf[1][1] = r4[3];
                }
#pragma unroll
                for (int nt = 0; nt < 2; ++nt) {
                    mma_bf16(acc[nt], ah, bhf[nt]);
                    mma_bf16(acc[nt], ah, blf[nt]);
                    mma_bf16(acc[nt], al, bhf[nt]);
                }
            }
            if (c != 0) {
                const int s = c - 1;
                const float abs_s = ab[s];
                const size_t mrowbase = ((size_t)(s*BB + b) * LL + i0 + wm) * 16;
                const size_t wi = (size_t)(jt * 2 + widx_base);
                unsigned mw0 = g_MB[mrowbase + (size_t)rquad * 16 + wi];
                unsigned mw1 = g_MB[mrowbase + (size_t)(rquad + 8) * 16 + wi];
#pragma unroll
                for (int nt = 0; nt < 2; ++nt) {
                    const int bp = bp0 + nt * 8;
                    S[nt][0] += (float)((mw0 >> bp) & 1u)     * (Sc[nt][0] + abs_s);
                    S[nt][1] += (float)((mw0 >> (bp+1)) & 1u) * (Sc[nt][1] + abs_s);
                    S[nt][2] += (float)((mw1 >> bp) & 1u)     * (Sc[nt][2] + abs_s);
                    S[nt][3] += (float)((mw1 >> (bp+1)) & 1u) * (Sc[nt][3] + abs_s);
                }
            }
        }

        // ---- spill S fp32 ----
        {
            const int rr = wm + rquad;
#pragma unroll
            for (int nt = 0; nt < 2; ++nt) {
                const int cc = wn + nt * 8 + (lane & 3) * 2;
                *(float2*)&sc[rr * 68 + cc]       = make_float2(S[nt][0], S[nt][1]);
                *(float2*)&sc[(rr + 8) * 68 + cc] = make_float2(S[nt][2], S[nt][3]);
            }
        }
        __syncthreads();

        // ---- online softmax (rows row0..+3): write P split + corr ----
        float amv[2];
        amv[0] = __ldg(amask + (size_t)b * LL + j0 + lane);
        amv[1] = __ldg(amask + (size_t)b * LL + j0 + lane + 32);

#pragma unroll
        for (int ii = 0; ii < 4; ++ii) {
            const int r = row0 + ii;
            float lg0 = sc[r * 68 + lane]      * 0.125f + amv[0];
            float lg1 = sc[r * 68 + lane + 32] * 0.125f + amv[1];
            float mt = warp_max(fmaxf(lg0, lg1));
            float mnew = fmaxf(mrow[ii], mt);
            float corr = __expf(mrow[ii] - mnew);
            mrow[ii] = mnew;
            float p0 = __expf(lg0 - mnew);
            float p1 = __expf(lg1 - mnew);
            __nv_bfloat16 p0h = __float2bfloat16_rn(p0);
            __nv_bfloat16 p1h = __float2bfloat16_rn(p1);
            *(__nv_bfloat16*)(smem + A_PH + r * 144 + lane * 2)        = p0h;
            *(__nv_bfloat16*)(smem + A_PH + r * 144 + (lane + 32) * 2) = p1h;
            *(__nv_bfloat16*)(smem + A_PL + r * 144 + lane * 2)
                = __float2bfloat16_rn(p0 - __bfloat162float(p0h));
            *(__nv_bfloat16*)(smem + A_PL + r * 144 + (lane + 32) * 2)
                = __float2bfloat16_rn(p1 - __bfloat162float(p1h));
            float psum = warp_sum(p0 + p1);
            lrow[ii] = lrow[ii] * corr + psum;
            if (lane == 0) crp[r] = corr;
        }
        __syncthreads();

        // ---- PV MMA: Ofr = Ofr*corr + P(16x64) x V^T(64->16d) ----
        {
            float c0 = crp[wm + rquad];
            float c1 = crp[wm + rquad + 8];
#pragma unroll
            for (int nt = 0; nt < 2; ++nt) {
                Ofr[nt][0] *= c0; Ofr[nt][1] *= c0;
                Ofr[nt][2] *= c1; Ofr[nt][3] *= c1;
            }
#pragma unroll
            for (int ks = 0; ks < 4; ++ks) {
                const uint32_t ko = ks * 32;
                uint32_t pah[4], pal[4], vbh[2][2], vbl[2][2];
                LDSM4(pah, a_pv + ko);
                LDSM4(pal, a_pv + PLOFF + ko);
                {
                    uint32_t r4[4];
                    LDSM4(r4, b_pv + ko);
                    vbh[0][0] = r4[0]; vbh[0][1] = r4[1];
                    vbh[1][0] = r4[2]; vbh[1][1] = r4[3];
                    LDSM4(r4, b_pv + VLOFF + ko);
                    vbl[0][0] = r4[0]; vbl[0][1] = r4[1];
                    vbl[1][0] = r4[2]; vbl[1][1] = r4[3];
                }
#pragma unroll
                for (int nt = 0; nt < 2; ++nt) {
                    mma_bf16(Ofr[nt], pah, vbh[nt]);
                    mma_bf16(Ofr[nt], pah, vbl[nt]);
                    mma_bf16(Ofr[nt], pal, vbh[nt]);
                }
            }
        }
    }

    // ---- finalize: publish lrow, then fragment owners write output ----
    if (lane == 0) {
#pragma unroll
        for (int ii = 0; ii < 4; ++ii) lrp[row0 + ii] = lrow[ii];
    }
    __syncthreads();
    {
        const float inv0 = 1.f / lrp[wm + rquad];
        const float inv1 = 1.f / lrp[wm + rquad + 8];
        const int ig0 = i0 + wm + rquad;
        const int ig1 = ig0 + 8;
        float* op0 = out + (size_t)(b * LL + ig0) * (HH*DD) + h * DD;
        float* op1 = out + (size_t)(b * LL + ig1) * (HH*DD) + h * DD;
#pragma unroll
        for (int nt = 0; nt < 2; ++nt) {
            const int d = d0 + nt * 8 + (lane & 3) * 2;
            *(float2*)(op0 + d) = make_float2(Ofr[nt][0] * inv0, Ofr[nt][1] * inv0);
            *(float2*)(op1 + d) = make_float2(Ofr[nt][2] * inv1, Ofr[nt][3] * inv1);
        }
    }
}

// =============================================================================
extern "C" void kernel_launch(void* const* d_in, const int* in_sizes, int n_in,
                              void* d_out, int out_size)
{
    const float* hs   = (const float*)d_in[0];
    const float* am   = (const float*)d_in[1];
    const float* smk  = (const float*)d_in[2];
    const float* Wq   = (const float*)d_in[3];
    const float* bq   = (const float*)d_in[4];
    const float* Wk   = (const float*)d_in[5];
    const float* bk   = (const float*)d_in[6];
    const float* Wv   = (const float*)d_in[7];
    const float* bv   = (const float*)d_in[8];
    const float* bili = (const float*)d_in[9];
    const float* absb = (const float*)d_in[10];
    float* out = (float*)d_out;

    pack_mask<<<(NSTRUCT*BB*LL*LL)/256, 256>>>(smk);
    cvt_hs<<<(BB*LL*HIDN/4)/256, 256>>>(hs);
    cvt_w<<<(3*HIDN*HIDN/4)/256, 256>>>(Wq, Wk, Wv);
    cvt_bili<<<(NSTRUCT*HH*DD*DD)/256, 256>>>(bili);

    cudaFuncSetAttribute(qkv_mma_kernel, cudaFuncAttributeMaxDynamicSharedMemorySize, QT_SMEM);
    qkv_mma_kernel<<<dim3(64, 6, 3), 256, QT_SMEM>>>(bq, bk, bv);

    cudaFuncSetAttribute(attn_kernel, cudaFuncAttributeMaxDynamicSharedMemorySize, A_TOT);
    attn_kernel<<<dim3(16, 192), 256, A_TOT>>>(am, absb, out);
}

// round 17
// speedup vs baseline: 1.3472x; 1.0517x over previous
#include <cuda_runtime.h>
#include <cuda_bf16.h>
#include <math.h>
#include <cstdint>

#define BB 16
#define LL 512
#define HIDN 768
#define HH 12
#define DD 64
#define NSTRUCT 5
#define BH (BB*HH)   // 192

// ---- warp MMA helpers ----
__device__ __forceinline__ uint32_t smem_u32(const void* p) {
    uint32_t a;
    asm("{ .reg .u64 t; cvta.to.shared.u64 t, %1; cvt.u32.u64 %0, t; }" : "=r"(a) : "l"(p));
    return a;
}
#define LDSM4(r, addr) \
    asm volatile("ldmatrix.sync.aligned.m8n8.x4.shared.b16 {%0,%1,%2,%3}, [%4];" \
        : "=r"((r)[0]), "=r"((r)[1]), "=r"((r)[2]), "=r"((r)[3]) : "r"(addr))

__device__ __forceinline__ void mma_bf16(float* c, const uint32_t* a, const uint32_t* b) {
    asm volatile("mma.sync.aligned.m16n8k16.row.col.f32.bf16.bf16.f32 "
        "{%0,%1,%2,%3}, {%4,%5,%6,%7}, {%8,%9}, {%0,%1,%2,%3};"
        : "+f"(c[0]), "+f"(c[1]), "+f"(c[2]), "+f"(c[3])
        : "r"(a[0]), "r"(a[1]), "r"(a[2]), "r"(a[3]), "r"(b[0]), "r"(b[1]));
}
#define CP_ASYNC16(sa, gp) \
    asm volatile("cp.async.cg.shared.global [%0], [%1], 16;" :: "r"(sa), "l"(gp))
#define CP_COMMIT() asm volatile("cp.async.commit_group;" ::: "memory")
#define CP_WAIT1()  asm volatile("cp.async.wait_group 1;" ::: "memory")
#define CP_WAIT0()  asm volatile("cp.async.wait_group 0;" ::: "memory")

// ---------------- scratch ----------------
__device__ unsigned g_MB[NSTRUCT * BB * LL * (LL/32)];
__device__ __nv_bfloat16 g_hsH[BB*LL*HIDN], g_hsL[BB*LL*HIDN];
__device__ __nv_bfloat16 g_WH [3*HIDN*HIDN], g_WL [3*HIDN*HIDN];
__device__ __nv_bfloat16 g_bTH[NSTRUCT*HH*DD*DD], g_bTL[NSTRUCT*HH*DD*DD];
__device__ __nv_bfloat16 g_QH [BH * LL * DD], g_QL [BH * LL * DD];
__device__ __nv_bfloat16 g_KH [BH * LL * DD], g_KL [BH * LL * DD];
__device__ __nv_bfloat16 g_VTH[BH * DD * LL], g_VTL[BH * DD * LL];   // V^T split [bh][d][l]

// =============================================================================
// Kernel 0a: pack structure mask to bits.
// =============================================================================
__global__ void __launch_bounds__(256) pack_mask(const float* __restrict__ smask)
{
    size_t e = (size_t)blockIdx.x * 256 + threadIdx.x;
    float v = smask[e];
    unsigned bal = __ballot_sync(0xffffffffu, v != 0.f);
    if ((threadIdx.x & 31) == 0) g_MB[e >> 5] = bal;
}

// =============================================================================
// split helpers + converters
// =============================================================================
__device__ __forceinline__ void split2(float a, float b, __nv_bfloat162* H, __nv_bfloat162* L) {
    __nv_bfloat16 ah = __float2bfloat16_rn(a), bh = __float2bfloat16_rn(b);
    __nv_bfloat16 al = __float2bfloat16_rn(a - __bfloat162float(ah));
    __nv_bfloat16 bl = __float2bfloat16_rn(b - __bfloat162float(bh));
    *H = __nv_bfloat162(ah, bh);
    *L = __nv_bfloat162(al, bl);
}
__global__ void __launch_bounds__(256) cvt_hs(const float* __restrict__ hs)
{
    size_t i = (size_t)blockIdx.x * 256 + threadIdx.x;
    float4 v = ((const float4*)hs)[i];
    __nv_bfloat162 h0, l0, h1, l1;
    split2(v.x, v.y, &h0, &l0);
    split2(v.z, v.w, &h1, &l1);
    ((__nv_bfloat162*)g_hsH)[2*i]   = h0;
    ((__nv_bfloat162*)g_hsH)[2*i+1] = h1;
    ((__nv_bfloat162*)g_hsL)[2*i]   = l0;
    ((__nv_bfloat162*)g_hsL)[2*i+1] = l1;
}
__global__ void __launch_bounds__(256) cvt_w(const float* __restrict__ Wq,
                                             const float* __restrict__ Wk,
                                             const float* __restrict__ Wv)
{
    size_t i = (size_t)blockIdx.x * 256 + threadIdx.x;
    const size_t per = (size_t)HIDN*HIDN/4;
    const float* src = (i < per) ? Wq : (i < 2*per) ? Wk : Wv;
    size_t loc = i % per;
    float4 v = ((const float4*)src)[loc];
    __nv_bfloat162 h0, l0, h1, l1;
    split2(v.x, v.y, &h0, &l0);
    split2(v.z, v.w, &h1, &l1);
    ((__nv_bfloat162*)g_WH)[2*i]   = h0;
    ((__nv_bfloat162*)g_WH)[2*i+1] = h1;
    ((__nv_bfloat162*)g_WL)[2*i]   = l0;
    ((__nv_bfloat162*)g_WL)[2*i+1] = l1;
}
__global__ void __launch_bounds__(256) cvt_bili(const float* __restrict__ bili)
{
    int idx = blockIdx.x * 256 + threadIdx.x;
    int sh = idx >> 12;
    int pq = idx & 4095;
    int p = pq >> 6, q = pq & 63;
    float v = bili[idx];
    __nv_bfloat16 hb = __float2bfloat16_rn(v);
    __nv_bfloat16 lb = __float2bfloat16_rn(v - __bfloat162float(hb));
    size_t dst = ((size_t)sh * 64 + q) * 64 + p;
    g_bTH[dst] = hb;
    g_bTL[dst] = lb;
}

// =============================================================================
// Kernel 1: QKV projection on mma.sync bf16 (split bf16x3).
// z=0 -> split g_QH/QL; z=1 -> split g_KH/KL; z=2 -> split V^T g_VTH/VTL.
// =============================================================================
#define QT_ROWB 80
#define QT_TILE (128 * QT_ROWB)
#define QT_STAGE (4 * QT_TILE)
#define QT_SMEM (2 * QT_STAGE)
#define NCHUNK (HIDN / 32)

__global__ void __launch_bounds__(256) qkv_mma_kernel(
    const float* __restrict__ bq, const float* __restrict__ bk, const float* __restrict__ bv)
{
    extern __shared__ __align__(16) char smem[];
    const uint32_t sb = smem_u32(smem);

    const int t = threadIdx.x, wid = t >> 5, lane = t & 31;
    const int m0 = blockIdx.x * 128;
    const int n0 = blockIdx.y * 128;
    const int z  = blockIdx.z;
    const float* bias = (z == 0) ? bq : (z == 1) ? bk : bv;
    const __nv_bfloat16* BHg = g_WH + (size_t)z * HIDN * HIDN;
    const __nv_bfloat16* BLg = g_WL + (size_t)z * HIDN * HIDN;

    const int wm = (wid & 1) * 64;
    const int wn = (wid >> 1) * 32;

    float C[4][4][4];
#pragma unroll
    for (int i = 0; i < 4; i++)
#pragma unroll
        for (int j = 0; j < 4; j++)
#pragma unroll
            for (int k = 0; k < 4; k++) C[i][j][k] = 0.f;

    const uint32_t a_off = (uint32_t)((wm + (lane & 7) + ((lane >> 3) & 1) * 8) * QT_ROWB
                                      + ((lane >> 4) * 8) * 2);
    const uint32_t b_off = (uint32_t)((wn + (lane & 7) + (lane >> 4) * 8) * QT_ROWB
                                      + (((lane >> 3) & 1) * 8) * 2);

    const int lr0 = t >> 2, lu0 = t & 3;
    const int lr1 = (t + 256) >> 2, lu1 = t & 3;

    {
        const int k0 = 0;
        uint32_t s0 = sb;
#pragma unroll
        for (int p = 0; p < 2; ++p) {
            int r = p ? lr1 : lr0, u = p ? lu1 : lu0;
            uint32_t so = (uint32_t)(r * QT_ROWB + u * 16);
            size_t ga = (size_t)(m0 + r) * HIDN + k0 + u * 8;
            size_t gb = (size_t)(n0 + r) * HIDN + k0 + u * 8;
            CP_ASYNC16(s0 + 0*QT_TILE + so, g_hsH + ga);
            CP_ASYNC16(s0 + 1*QT_TILE + so, g_hsL + ga);
            CP_ASYNC16(s0 + 2*QT_TILE + so, BHg + gb);
            CP_ASYNC16(s0 + 3*QT_TILE + so, BLg + gb);
        }
        CP_COMMIT();
    }

    for (int ch = 0; ch < NCHUNK; ++ch) {
        if (ch + 1 < NCHUNK) {
            const int k0 = (ch + 1) * 32;
            uint32_t s1 = sb + ((ch + 1) & 1) * QT_STAGE;
#pragma unroll
            for (int p = 0; p < 2; ++p) {
                int r = p ? lr1 : lr0, u = p ? lu1 : lu0;
                uint32_t so = (uint32_t)(r * QT_ROWB + u * 16);
                size_t ga = (size_t)(m0 + r) * HIDN + k0 + u * 8;
                size_t gb = (size_t)(n0 + r) * HIDN + k0 + u * 8;
                CP_ASYNC16(s1 + 0*QT_TILE + so, g_hsH + ga);
                CP_ASYNC16(s1 + 1*QT_TILE + so, g_hsL + ga);
                CP_ASYNC16(s1 + 2*QT_TILE + so, BHg + gb);
                CP_ASYNC16(s1 + 3*QT_TILE + so, BLg + gb);
            }
            CP_COMMIT();
            CP_WAIT1();
        } else {
            CP_WAIT0();
        }
        __syncthreads();

        const uint32_t st = sb + (ch & 1) * QT_STAGE;
        const uint32_t aH = st + 0*QT_TILE + a_off;
        const uint32_t aL = st + 1*QT_TILE + a_off;
        const uint32_t bHb = st + 2*QT_TILE + b_off;
        const uint32_t bLb = st + 3*QT_TILE + b_off;

#pragma unroll
        for (int ks = 0; ks < 2; ++ks) {
            const uint32_t ko = ks * 32;
            uint32_t ah[4][4], al[4][4], bh[4][2], bl[4][2];
#pragma unroll
            for (int mt = 0; mt < 4; ++mt) {
                LDSM4(ah[mt], aH + mt * 16 * QT_ROWB + ko);
                LDSM4(al[mt], aL + mt * 16 * QT_ROWB + ko);
            }
#pragma unroll
            for (int p = 0; p < 2; ++p) {
                uint32_t r4[4];
                LDSM4(r4, bHb + p * 16 * QT_ROWB + ko);
                bh[2*p][0] = r4[0]; bh[2*p][1] = r4[1];
                bh[2*p+1][0] = r4[2]; bh[2*p+1][1] = r4[3];
                LDSM4(r4, bLb + p * 16 * QT_ROWB + ko);
                bl[2*p][0] = r4[0]; bl[2*p][1] = r4[1];
                bl[2*p+1][0] = r4[2]; bl[2*p+1][1] = r4[3];
            }
#pragma unroll
            for (int mt = 0; mt < 4; ++mt)
#pragma unroll
                for (int nt = 0; nt < 4; ++nt) {
                    mma_bf16(C[mt][nt], ah[mt], bh[nt]);
                    mma_bf16(C[mt][nt], ah[mt], bl[nt]);
                    mma_bf16(C[mt][nt], al[mt], bh[nt]);
                }
        }
        __syncthreads();
    }

    // ---- epilogue ----
#pragma unroll
    for (int mt = 0; mt < 4; ++mt) {
        const int m = m0 + wm + mt * 16 + (lane >> 2);
        const int b = m >> 9, l = m & 511;
#pragma unroll
        for (int nt = 0; nt < 4; ++nt) {
            const int n = n0 + wn + nt * 8 + (lane & 3) * 2;
            const int hd = n >> 6, d = n & 63;
            const float b0 = __ldg(bias + n), b1 = __ldg(bias + n + 1);
            float v00 = C[mt][nt][0] + b0, v01 = C[mt][nt][1] + b1;
            float v10 = C[mt][nt][2] + b0, v11 = C[mt][nt][3] + b1;
            if (z == 2) {
                const size_t vb = (size_t)(b * HH + hd) * DD;
                __nv_bfloat16 h00 = __float2bfloat16_rn(v00);
                __nv_bfloat16 h01 = __float2bfloat16_rn(v01);
                __nv_bfloat16 h10 = __float2bfloat16_rn(v10);
                __nv_bfloat16 h11 = __float2bfloat16_rn(v11);
                g_VTH[(vb + d)     * LL + l]     = h00;
                g_VTH[(vb + d + 1) * LL + l]     = h01;
                g_VTH[(vb + d)     * LL + l + 8] = h10;
                g_VTH[(vb + d + 1) * LL + l + 8] = h11;
                g_VTL[(vb + d)     * LL + l]     = __float2bfloat16_rn(v00 - __bfloat162float(h00));
                g_VTL[(vb + d + 1) * LL + l]     = __float2bfloat16_rn(v01 - __bfloat162float(h01));
                g_VTL[(vb + d)     * LL + l + 8] = __float2bfloat16_rn(v10 - __bfloat162float(h10));
                g_VTL[(vb + d + 1) * LL + l + 8] = __float2bfloat16_rn(v11 - __bfloat162float(h11));
            } else {
                const size_t o1 = ((size_t)(b * HH + hd) * LL + l) * DD + d;
                const size_t o2 = ((size_t)(b * HH + hd) * LL + (l + 8)) * DD + d;
                __nv_bfloat16* dH = (z == 0) ? g_QH : g_KH;
                __nv_bfloat16* dL = (z == 0) ? g_QL : g_KL;
                __nv_bfloat162 hh, llo;
                split2(v00, v01, &hh, &llo);
                *(__nv_bfloat162*)(dH + o1) = hh;
                *(__nv_bfloat162*)(dL + o1) = llo;
                split2(v10, v11, &hh, &llo);
                *(__nv_bfloat162*)(dH + o2) = hh;
                *(__nv_bfloat162*)(dL + o2) = llo;
            }
        }
    }
}

// =============================================================================
// Kernel 3: fused attention, QB fused, PV via MMA, cp.async K/V overlap.
// 32 q-rows/block, 64-wide j-tiles, 2 blocks/SM.
// =============================================================================
#define A_QH 0
#define A_QL (A_QH + 6*32*144)        // 27648
#define A_KH (A_QL + 6*32*144)        // 55296
#define A_KL (A_KH + 64*144)          // 64512
#define A_VH (A_KL + 64*144)          // 73728
#define A_VL (A_VH + 64*144)          // 82944
#define A_SC (A_VL + 64*144)          // 92160  (fp32 32x68)
#define A_PH (A_SC + 32*68*4)         // 100864
#define A_PL (A_PH + 32*144)          // 105472
#define A_CR (A_PL + 32*144)          // 110080 (corr[32])
#define A_LR (A_CR + 128)             // 110208 (lrow[32])
#define A_TOT (A_LR + 128)            // 110336

__device__ __forceinline__ float warp_max(float v) {
#pragma unroll
    for (int off = 16; off > 0; off >>= 1)
        v = fmaxf(v, __shfl_xor_sync(0xffffffffu, v, off));
    return v;
}
__device__ __forceinline__ float warp_sum(float v) {
#pragma unroll
    for (int off = 16; off > 0; off >>= 1)
        v += __shfl_xor_sync(0xffffffffu, v, off);
    return v;
}

__global__ void __launch_bounds__(256) attn_kernel(
    const float* __restrict__ amask,
    const float* __restrict__ absb,
    float* __restrict__ out)
{
    extern __shared__ __align__(16) char smem[];
    const uint32_t sb = smem_u32(smem);
    float* sc  = (float*)(smem + A_SC);
    float* crp = (float*)(smem + A_CR);
    float* lrp = (float*)(smem + A_LR);

    const int t    = threadIdx.x;
    const int w    = t >> 5;
    const int lane = t & 31;
    const int bh   = blockIdx.y;
    const int b = bh / HH, h = bh % HH;
    const int i0 = blockIdx.x * 32;

    const __nv_bfloat16* KHb = g_KH + (size_t)bh * LL * DD;
    const __nv_bfloat16* KLb = g_KL + (size_t)bh * LL * DD;
    const __nv_bfloat16* VHb = g_VTH + (size_t)bh * DD * LL;
    const __nv_bfloat16* VLb = g_VTL + (size_t)bh * DD * LL;

    const uint32_t QLOFF = A_QL - A_QH;
    const uint32_t KLOFF = A_KL - A_KH;
    const uint32_t VLOFF = A_VL - A_VH;
    const uint32_t PLOFF = A_PL - A_PH;

    // K loader indices: f = t and t+256 over 512
    const int kr0 = t >> 3, ku0 = t & 7;
    const int kr1 = (t + 256) >> 3, ku1 = t & 7;
    // V loader indices: f = t over 256
    const int vd0 = t >> 2, vu0 = t & 3;

    // ---- load q (component 0) ----
    for (int f = t; f < 32 * 8; f += 256) {
        int r = f >> 3, u = f & 7;
        const size_t go = (size_t)bh * LL * DD + (size_t)(i0 + r) * DD + u * 8;
        char* p = smem + r * 144 + u * 16;
        *(uint4*)(p + A_QH) = *(const uint4*)(g_QH + go);
        *(uint4*)(p + A_QL) = *(const uint4*)(g_QL + go);
    }

    // ---- compute QB_s into qall slots c=1..5 ----
    {
        const int wmq = (w & 1) * 16;
        const int wnq = (w >> 1) * 16;
        const uint32_t aq = sb + A_QH
            + (uint32_t)((wmq + (lane & 7) + ((lane >> 3) & 1) * 8) * 144 + (lane >> 4) * 16);
        const uint32_t bq_ = sb + A_KH
            + (uint32_t)((wnq + (lane & 7) + (lane >> 4) * 8) * 144 + ((lane >> 3) & 1) * 16);
        for (int s = 0; s < NSTRUCT; ++s) {
            __syncthreads();
            const size_t boff = (size_t)(s * HH + h) * 64 * 64;
            for (int f = t; f < 512; f += 256) {
                int r = f >> 3, u = f & 7;
                char* p = smem + r * 144 + u * 16;
                *(uint4*)(p + A_KH) = *(const uint4*)(g_bTH + boff + (size_t)r * 64 + u * 8);
                *(uint4*)(p + A_KL) = *(const uint4*)(g_bTL + boff + (size_t)r * 64 + u * 8);
            }
            __syncthreads();

            float C[2][4];
#pragma unroll
            for (int nt = 0; nt < 2; ++nt)
#pragma unroll
                for (int k = 0; k < 4; ++k) C[nt][k] = 0.f;
#pragma unroll
            for (int ks = 0; ks < 4; ++ks) {
                const uint32_t ko = ks * 32;
                uint32_t ah[4], al[4], bhf[2][2], blf[2][2];
                LDSM4(ah, aq + ko);
                LDSM4(al, aq + QLOFF + ko);
                {
                    uint32_t r4[4];
                    LDSM4(r4, bq_ + ko);
                    bhf[0][0] = r4[0]; bhf[0][1] = r4[1];
                    bhf[1][0] = r4[2]; bhf[1][1] = r4[3];
                    LDSM4(r4, bq_ + KLOFF + ko);
                    blf[0][0] = r4[0]; blf[0][1] = r4[1];
                    blf[1][0] = r4[2]; blf[1][1] = r4[3];
                }
#pragma unroll
                for (int nt = 0; nt < 2; ++nt) {
                    mma_bf16(C[nt], ah, bhf[nt]);
                    mma_bf16(C[nt], ah, blf[nt]);
                    mma_bf16(C[nt], al, bhf[nt]);
                }
            }
            const int r0 = wmq + (lane >> 2);
#pragma unroll
            for (int nt = 0; nt < 2; ++nt) {
                const int col = wnq + nt * 8 + (lane & 3) * 2;
                __nv_bfloat162 hh, llo;
                split2(C[nt][0], C[nt][1], &hh, &llo);
                *(__nv_bfloat162*)(smem + A_QH + ((s+1)*32 + r0) * 144 + col * 2) = hh;
                *(__nv_bfloat162*)(smem + A_QL + ((s+1)*32 + r0) * 144 + col * 2) = llo;
                split2(C[nt][2], C[nt][3], &hh, &llo);
                *(__nv_bfloat162*)(smem + A_QH + ((s+1)*32 + r0 + 8) * 144 + col * 2) = hh;
                *(__nv_bfloat162*)(smem + A_QL + ((s+1)*32 + r0 + 8) * 144 + col * 2) = llo;
            }
        }
    }
    __syncthreads();   // QB stores done; A_KH free for K tiles

    // ---- preload K(0) then V(0), separate commit groups ----
    {
        // K(0)
        {
            uint32_t so0 = (uint32_t)(kr0 * 144 + ku0 * 16);
            uint32_t so1 = (uint32_t)(kr1 * 144 + ku1 * 16);
            size_t g0 = (size_t)kr0 * DD + ku0 * 8;
            size_t g1 = (size_t)kr1 * DD + ku1 * 8;
            CP_ASYNC16(sb + A_KH + so0, KHb + g0);
            CP_ASYNC16(sb + A_KL + so0, KLb + g0);
            CP_ASYNC16(sb + A_KH + so1, KHb + g1);
            CP_ASYNC16(sb + A_KL + so1, KLb + g1);
            CP_COMMIT();
        }
        // V(0)
        {
            uint32_t so = (uint32_t)(vd0 * 144 + vu0 * 32);
            size_t go = (size_t)vd0 * LL + vu0 * 16;
            CP_ASYNC16(sb + A_VH + so,      VHb + go);
            CP_ASYNC16(sb + A_VH + so + 16, VHb + go + 8);
            CP_ASYNC16(sb + A_VL + so,      VLb + go);
            CP_ASYNC16(sb + A_VL + so + 16, VLb + go + 8);
            CP_COMMIT();
        }
    }

    float ab[NSTRUCT];
#pragma unroll
    for (int s = 0; s < NSTRUCT; ++s) ab[s] = __ldg(absb + s*HH + h);

    float mrow[4], lrow[4];
#pragma unroll
    for (int i = 0; i < 4; ++i) { mrow[i] = -1e30f; lrow[i] = 0.f; }

    const int row0 = w * 4;
    const int wm = (w & 1) * 16;
    const int wn = (w >> 1) * 16;
    const int d0 = (w >> 1) * 16;

    float Ofr[2][4];
#pragma unroll
    for (int nt = 0; nt < 2; ++nt)
#pragma unroll
        for (int k = 0; k < 4; ++k) Ofr[nt][k] = 0.f;

    const uint32_t a_base = sb + A_QH
        + (uint32_t)((wm + (lane & 7) + ((lane >> 3) & 1) * 8) * 144 + (lane >> 4) * 16);
    const uint32_t b_base = sb + A_KH
        + (uint32_t)((wn + (lane & 7) + (lane >> 4) * 8) * 144 + ((lane >> 3) & 1) * 16);
    const uint32_t a_pv = sb + A_PH
        + (uint32_t)((wm + (lane & 7) + ((lane >> 3) & 1) * 8) * 144 + (lane >> 4) * 16);
    const uint32_t b_pv = sb + A_VH
        + (uint32_t)((d0 + (lane & 7) + (lane >> 4) * 8) * 144 + ((lane >> 3) & 1) * 16);

    const int widx_base = (wn >> 5);
    const int bp0 = (wn & 31) + (lane & 3) * 2;
    const int rquad = lane >> 2;

    for (int jt = 0; jt < 8; ++jt) {
        const int j0 = jt * 64;
        const int jn = (jt + 1 < 8) ? (jt + 1) : 7;   // clamp (uniform group count)
        CP_WAIT1();        // K(jt) ready (V(jt) group may still be in flight)
        __syncthreads();

        // ---- S MMA: 6 components ----
        float S[2][4];
#pragma unroll
        for (int j = 0; j < 2; ++j)
#pragma unroll
            for (int k = 0; k < 4; ++k) S[j][k] = 0.f;

        for (int c = 0; c < 6; ++c) {
            float Sc[2][4];
            float (*acc)[4] = (c == 0) ? S : Sc;
            if (c != 0) {
#pragma unroll
                for (int j = 0; j < 2; ++j)
#pragma unroll
                    for (int k = 0; k < 4; ++k) Sc[j][k] = 0.f;
            }
            const uint32_t aH = a_base + (uint32_t)(c * 32 * 144);
#pragma unroll
            for (int ks = 0; ks < 4; ++ks) {
                const uint32_t ko = ks * 32;
                uint32_t ah[4], al[4], bhf[2][2], blf[2][2];
                LDSM4(ah, aH + ko);
                LDSM4(al, aH + QLOFF + ko);
                {
                    uint32_t r4[4];
                    LDSM4(r4, b_base + ko);
                    bhf[0][0] = r4[0]; bhf[0][1] = r4[1];
                    bhf[1][0] = r4[2]; bhf[1][1] = r4[3];
                    LDSM4(r4, b_base + KLOFF + ko);
                    blf[0][0] = r4[0]; blf[0][1] = r4[1];
                    blf[1][0] = r4[2]; blf[1][1] = r4[3];
                }
#pragma unroll
                for (int nt = 0; nt < 2; ++nt) {
                    mma_bf16(acc[nt], ah, bhf[nt]);
                    mma_bf16(acc[nt], ah, blf[nt]);
                    mma_bf16(acc[nt], al, bhf[nt]);
                }
            }
            if (c != 0) {
                const int s = c - 1;
                const float abs_s = ab[s];
                const size_t mrowbase = ((size_t)(s*BB + b) * LL + i0 + wm) * 16;
                const size_t wi = (size_t)(jt * 2 + widx_base);
                unsigned mw0 = g_MB[mrowbase + (size_t)rquad * 16 + wi];
                unsigned mw1 = g_MB[mrowbase + (size_t)(rquad + 8) * 16 + wi];
#pragma unroll
                for (int nt = 0; nt < 2; ++nt) {
                    const int bp = bp0 + nt * 8;
                    S[nt][0] += (float)((mw0 >> bp) & 1u)     * (Sc[nt][0] + abs_s);
                    S[nt][1] += (float)((mw0 >> (bp+1)) & 1u) * (Sc[nt][1] + abs_s);
                    S[nt][2] += (float)((mw1 >> bp) & 1u)     * (Sc[nt][2] + abs_s);
                    S[nt][3] += (float)((mw1 >> (bp+1)) & 1u) * (Sc[nt][3] + abs_s);
                }
            }
        }

        // ---- spill S fp32 ----
        {
            const int rr = wm + rquad;
#pragma unroll
            for (int nt = 0; nt < 2; ++nt) {
                const int cc = wn + nt * 8 + (lane & 3) * 2;
                *(float2*)&sc[rr * 68 + cc]       = make_float2(S[nt][0], S[nt][1]);
                *(float2*)&sc[(rr + 8) * 68 + cc] = make_float2(S[nt][2], S[nt][3]);
            }
        }
        __syncthreads();   // S visible; also: all warps done reading K(jt)

        // ---- issue K(jt+1) (overlaps softmax + PV) ----
        {
            uint32_t so0 = (uint32_t)(kr0 * 144 + ku0 * 16);
            uint32_t so1 = (uint32_t)(kr1 * 144 + ku1 * 16);
            size_t g0 = (size_t)(jn * 64 + kr0) * DD + ku0 * 8;
            size_t g1 = (size_t)(jn * 64 + kr1) * DD + ku1 * 8;
            CP_ASYNC16(sb + A_KH + so0, KHb + g0);
            CP_ASYNC16(sb + A_KL + so0, KLb + g0);
            CP_ASYNC16(sb + A_KH + so1, KHb + g1);
            CP_ASYNC16(sb + A_KL + so1, KLb + g1);
            CP_COMMIT();
        }

        // ---- online softmax (rows row0..+3): write P split + corr ----
        float amv[2];
        amv[0] = __ldg(amask + (size_t)b * LL + j0 + lane);
        amv[1] = __ldg(amask + (size_t)b * LL + j0 + lane + 32);

#pragma unroll
        for (int ii = 0; ii < 4; ++ii) {
            const int r = row0 + ii;
            float lg0 = sc[r * 68 + lane]      * 0.125f + amv[0];
            float lg1 = sc[r * 68 + lane + 32] * 0.125f + amv[1];
            float mt = warp_max(fmaxf(lg0, lg1));
            float mnew = fmaxf(mrow[ii], mt);
            float corr = __expf(mrow[ii] - mnew);
            mrow[ii] = mnew;
            float p0 = __expf(lg0 - mnew);
            float p1 = __expf(lg1 - mnew);
            __nv_bfloat16 p0h = __float2bfloat16_rn(p0);
            __nv_bfloat16 p1h = __float2bfloat16_rn(p1);
            *(__nv_bfloat16*)(smem + A_PH + r * 144 + lane * 2)        = p0h;
            *(__nv_bfloat16*)(smem + A_PH + r * 144 + (lane + 32) * 2) = p1h;
            *(__nv_bfloat16*)(smem + A_PL + r * 144 + lane * 2)
                = __float2bfloat16_rn(p0 - __bfloat162float(p0h));
            *(__nv_bfloat16*)(smem + A_PL + r * 144 + (lane + 32) * 2)
                = __float2bfloat16_rn(p1 - __bfloat162float(p1h));
            float psum = warp_sum(p0 + p1);
            lrow[ii] = lrow[ii] * corr + psum;
            if (lane == 0) crp[r] = corr;
        }
        CP_WAIT1();        // V(jt) ready (K(jt+1) group may pend)
        __syncthreads();

        // ---- PV MMA: Ofr = Ofr*corr + P(16x64) x V^T(64->16d) ----
        {
            float c0 = crp[wm + rquad];
            float c1 = crp[wm + rquad + 8];
#pragma unroll
            for (int nt = 0; nt < 2; ++nt) {
                Ofr[nt][0] *= c0; Ofr[nt][1] *= c0;
                Ofr[nt][2] *= c1; Ofr[nt][3] *= c1;
            }
#pragma unroll
            for (int ks = 0; ks < 4; ++ks) {
                const uint32_t ko = ks * 32;
                uint32_t pah[4], pal[4], vbh[2][2], vbl[2][2];
                LDSM4(pah, a_pv + ko);
                LDSM4(pal, a_pv + PLOFF + ko);
                {
                    uint32_t r4[4];
                    LDSM4(r4, b_pv + ko);
                    vbh[0][0] = r4[0]; vbh[0][1] = r4[1];
                    vbh[1][0] = r4[2]; vbh[1][1] = r4[3];
                    LDSM4(r4, b_pv + VLOFF + ko);
                    vbl[0][0] = r4[0]; vbl[0][1] = r4[1];
                    vbl[1][0] = r4[2]; vbl[1][1] = r4[3];
                }
#pragma unroll
                for (int nt = 0; nt < 2; ++nt) {
                    mma_bf16(Ofr[nt], pah, vbh[nt]);
                    mma_bf16(Ofr[nt], pah, vbl[nt]);
                    mma_bf16(Ofr[nt], pal, vbh[nt]);
                }
            }
        }
        __syncthreads();   // all warps done reading V(jt)

        // ---- issue V(jt+1) (overlaps next top wait + S-MMA) ----
        {
            uint32_t so = (uint32_t)(vd0 * 144 + vu0 * 32);
            size_t go = (size_t)vd0 * LL + jn * 64 + vu0 * 16;
            CP_ASYNC16(sb + A_VH + so,      VHb + go);
            CP_ASYNC16(sb + A_VH + so + 16, VHb + go + 8);
            CP_ASYNC16(sb + A_VL + so,      VLb + go);
            CP_ASYNC16(sb + A_VL + so + 16, VLb + go + 8);
            CP_COMMIT();
        }
    }
    CP_WAIT0();

    // ---- finalize ----
    if (lane == 0) {
#pragma unroll
        for (int ii = 0; ii < 4; ++ii) lrp[row0 + ii] = lrow[ii];
    }
    __syncthreads();
    {
        const float inv0 = 1.f / lrp[wm + rquad];
        const float inv1 = 1.f / lrp[wm + rquad + 8];
        const int ig0 = i0 + wm + rquad;
        const int ig1 = ig0 + 8;
        float* op0 = out + (size_t)(b * LL + ig0) * (HH*DD) + h * DD;
        float* op1 = out + (size_t)(b * LL + ig1) * (HH*DD) + h * DD;
#pragma unroll
        for (int nt = 0; nt < 2; ++nt) {
            const int d = d0 + nt * 8 + (lane & 3) * 2;
            *(float2*)(op0 + d) = make_float2(Ofr[nt][0] * inv0, Ofr[nt][1] * inv0);
            *(float2*)(op1 + d) = make_float2(Ofr[nt][2] * inv1, Ofr[nt][3] * inv1);
        }
    }
}

// =============================================================================
extern "C" void kernel_launch(void* const* d_in, const int* in_sizes, int n_in,
                              void* d_out, int out_size)
{
    const float* hs   = (const float*)d_in[0];
    const float* am   = (const float*)d_in[1];
    const float* smk  = (const float*)d_in[2];
    const float* Wq   = (const float*)d_in[3];
    const float* bq   = (const float*)d_in[4];
    const float* Wk   = (const float*)d_in[5];
    const float* bk   = (const float*)d_in[6];
    const float* Wv   = (const float*)d_in[7];
    const float* bv   = (const float*)d_in[8];
    const float* bili = (const float*)d_in[9];
    const float* absb = (const float*)d_in[10];
    float* out = (float*)d_out;

    pack_mask<<<(NSTRUCT*BB*LL*LL)/256, 256>>>(smk);
    cvt_hs<<<(BB*LL*HIDN/4)/256, 256>>>(hs);
    cvt_w<<<(3*HIDN*HIDN/4)/256, 256>>>(Wq, Wk, Wv);
    cvt_bili<<<(NSTRUCT*HH*DD*DD)/256, 256>>>(bili);

    cudaFuncSetAttribute(qkv_mma_kernel, cudaFuncAttributeMaxDynamicSharedMemorySize, QT_SMEM);
    qkv_mma_kernel<<<dim3(64, 6, 3), 256, QT_SMEM>>>(bq, bk, bv);

    cudaFuncSetAttribute(attn_kernel, cudaFuncAttributeMaxDynamicSharedMemorySize, A_TOT);
    attn_kernel<<<dim3(16, 192), 256, A_TOT>>>(am, absb, out);
}